// round 6
// baseline (speedup 1.0000x reference)
#include <cuda_runtime.h>
#include <stdint.h>
#include <math.h>

#define V_NUM 6890
#define B_NUM 512
#define J_NUM 24
#define KP    207   // (J-1)*9
#define NBETA 10
#define VC    (V_NUM*3)   // 20670
#define KT    23          // 207 = 9 * 23 exactly
#define NTILE 9
#define BT    64          // batches per block
#define VT    32          // vertices per block
#define NTHR  256

typedef unsigned long long ull;
typedef unsigned int u32;

__constant__ int c_par[24] = {-1,0,0,0,1,2,3,4,5,6,7,8,9,9,9,12,13,14,16,17,18,19,20,21};

// Scratch (no allocations allowed)
__device__ float g_Jt0[J_NUM*3];
__device__ float g_JS[J_NUM*3*NBETA];
__device__ __align__(16) float g_pfT[KP*B_NUM];          // transposed pose_feature [k][b]
__device__ __align__(16) float g_A2[(B_NUM/2)*580];      // batch-pair-interleaved affines, padded rows

// ---- packed f32x2 helpers (Blackwell FFMA2 path) -------------------------
__device__ __forceinline__ ull pk(float l, float h) {
    ull r; asm("mov.b64 %0, {%1, %2};" : "=l"(r) : "f"(l), "f"(h)); return r;
}
__device__ __forceinline__ float ulo(ull v) {
    float l, h; asm("mov.b64 {%0, %1}, %2;" : "=f"(l), "=f"(h) : "l"(v)); return l;
}
__device__ __forceinline__ float uhi(ull v) {
    float l, h; asm("mov.b64 {%0, %1}, %2;" : "=f"(l), "=f"(h) : "l"(v)); return h;
}
__device__ __forceinline__ ull ffma2(ull a, ull b, ull c) {
    ull r; asm("fma.rn.f32x2 %0, %1, %2, %3;" : "=l"(r) : "l"(a), "l"(b), "l"(c)); return r;
}

// ---- cp.async helpers -----------------------------------------------------
__device__ __forceinline__ void cp16(u32 dst, const void* src) {
    asm volatile("cp.async.ca.shared.global [%0], [%1], 16;" :: "r"(dst), "l"(src));
}
__device__ __forceinline__ void cp8(u32 dst, const void* src) {
    asm volatile("cp.async.ca.shared.global [%0], [%1], 8;" :: "r"(dst), "l"(src));
}
__device__ __forceinline__ void cp4(u32 dst, const void* src) {
    asm volatile("cp.async.ca.shared.global [%0], [%1], 4;" :: "r"(dst), "l"(src));
}
__device__ __forceinline__ void cp_commit() { asm volatile("cp.async.commit_group;"); }
template<int N> __device__ __forceinline__ void cp_wait() {
    asm volatile("cp.async.wait_group %0;" :: "n"(N));
}

// ---------------------------------------------------------------------------
__global__ void zero_k()
{
    int t = threadIdx.x;
    if (t < J_NUM*3) g_Jt0[t] = 0.0f;
    for (int i = t; i < J_NUM*30; i += 256) g_JS[i] = 0.0f;
}

// ---------------------------------------------------------------------------
__global__ void regress_k(const float* __restrict__ Jreg,
                          const float* __restrict__ vt,
                          const float* __restrict__ sd)
{
    int j = blockIdx.x;
    int chunk = blockIdx.y;                 // 14 chunks
    const int CH = (V_NUM + 13) / 14;       // 493
    int v0 = chunk * CH;
    int v1 = min(v0 + CH, V_NUM);
    int t = threadIdx.x;                    // 256
    int lane = t & 31, w = t >> 5;

    float acc[33];
#pragma unroll
    for (int i = 0; i < 33; i++) acc[i] = 0.f;
    for (int v = v0 + t; v < v1; v += 256) {
        float r = Jreg[j*V_NUM + v];
#pragma unroll
        for (int c = 0; c < 3; c++) acc[c] += r * vt[v*3+c];
#pragma unroll
        for (int i = 0; i < 30; i++) acc[3+i] += r * sd[v*30+i];
    }
    __shared__ float red[8][33];
#pragma unroll
    for (int i = 0; i < 33; i++) {
        float v = acc[i];
#pragma unroll
        for (int o = 16; o; o >>= 1) v += __shfl_xor_sync(0xffffffffu, v, o);
        if (lane == 0) red[w][i] = v;
    }
    __syncthreads();
    if (t < 33) {
        float s = 0.f;
#pragma unroll
        for (int ww = 0; ww < 8; ww++) s += red[ww][t];
        if (t < 3) atomicAdd(&g_Jt0[j*3 + t], s);
        else       atomicAdd(&g_JS[j*30 + (t-3)], s);
    }
}

// ---------------------------------------------------------------------------
__global__ void pose_k(const float* __restrict__ pose,
                       const float* __restrict__ betas,
                       const float* __restrict__ trans)
{
    int b = blockIdx.x;
    int lane = threadIdx.x;   // 32
    __shared__ float R[24][9];
    __shared__ float Jt[24][3];
    __shared__ float Tl[24][12];
    __shared__ float Tw[24][12];

    if (lane < 24) {
        float rx = pose[b*72 + lane*3 + 0];
        float ry = pose[b*72 + lane*3 + 1];
        float rz = pose[b*72 + lane*3 + 2];
        float ang = sqrtf(rx*rx + ry*ry + rz*rz + 1e-16f);
        float inv = 1.0f/ang;
        float ax = rx*inv, ay = ry*inv, az = rz*inv;
        float s = sinf(ang), c = cosf(ang), tt = 1.0f - c;
        R[lane][0] = c + tt*ax*ax;    R[lane][1] = tt*ax*ay - s*az; R[lane][2] = tt*ax*az + s*ay;
        R[lane][3] = tt*ax*ay + s*az; R[lane][4] = c + tt*ay*ay;    R[lane][5] = tt*ay*az - s*ax;
        R[lane][6] = tt*ax*az - s*ay; R[lane][7] = tt*ay*az + s*ax; R[lane][8] = c + tt*az*az;

        float bet[NBETA];
#pragma unroll
        for (int k = 0; k < NBETA; k++) bet[k] = betas[b*NBETA + k];
#pragma unroll
        for (int c3 = 0; c3 < 3; c3++) {
            float a = g_Jt0[lane*3 + c3];
#pragma unroll
            for (int k = 0; k < NBETA; k++) a += g_JS[lane*30 + c3*10 + k] * bet[k];
            Jt[lane][c3] = a;
        }
    }
    __syncwarp();

    for (int idx = lane; idx < KP; idx += 32) {
        int j = idx/9 + 1, e = idx%9;
        float v = R[j][e] - ((e == 0 || e == 4 || e == 8) ? 1.0f : 0.0f);
        g_pfT[idx*B_NUM + b] = v;
    }

    if (lane < 24) {
        float tx, ty, tz;
        if (lane == 0) { tx = Jt[0][0]; ty = Jt[0][1]; tz = Jt[0][2]; }
        else {
            int p = c_par[lane];
            tx = Jt[lane][0] - Jt[p][0];
            ty = Jt[lane][1] - Jt[p][1];
            tz = Jt[lane][2] - Jt[p][2];
        }
        Tl[lane][0] = R[lane][0]; Tl[lane][1] = R[lane][1]; Tl[lane][2]  = R[lane][2]; Tl[lane][3]  = tx;
        Tl[lane][4] = R[lane][3]; Tl[lane][5] = R[lane][4]; Tl[lane][6]  = R[lane][5]; Tl[lane][7]  = ty;
        Tl[lane][8] = R[lane][6]; Tl[lane][9] = R[lane][7]; Tl[lane][10] = R[lane][8]; Tl[lane][11] = tz;
    }
    __syncwarp();
    if (lane < 12) Tw[0][lane] = Tl[0][lane];
    __syncwarp();
    for (int i = 1; i < 24; i++) {
        if (lane < 12) {
            int r = lane >> 2, cc = lane & 3;
            int p = c_par[i];
            float v = Tw[p][r*4+0]*Tl[i][0+cc] + Tw[p][r*4+1]*Tl[i][4+cc] + Tw[p][r*4+2]*Tl[i][8+cc];
            if (cc == 3) v += Tw[p][r*4+3];
            Tw[i][lane] = v;
        }
        __syncwarp();
    }
    if (lane < 24) {
        float jx = Jt[lane][0], jy = Jt[lane][1], jz = Jt[lane][2];
        size_t base = (size_t)(b >> 1) * 580 + (b & 1);
#pragma unroll
        for (int r = 0; r < 3; r++) {
            float r0 = Tw[lane][r*4+0], r1 = Tw[lane][r*4+1], r2 = Tw[lane][r*4+2];
            float t3 = Tw[lane][r*4+3] - (r0*jx + r1*jy + r2*jz) + trans[b*3+r];
            int e = lane*12 + r*4;
            g_A2[base + (e+0)*2] = r0;
            g_A2[base + (e+1)*2] = r1;
            g_A2[base + (e+2)*2] = r2;
            g_A2[base + (e+3)*2] = t3;
        }
    }
}

// ---------------------------------------------------------------------------
// Main fused kernel: 256 threads, block tile 32v x 64b, thread tile 4v x 2b.
// Static 35KB smem -> 3 CTAs/SM (24 warps). A read from L2-resident gmem.
// ---------------------------------------------------------------------------
#define PD_F  (KT*96)           // 2208
#define PF_F  (KT*64)           // 1472
#define BUF_F (PD_F + PF_F)     // 3680
#define SW_OFF (2*BUF_F)        // 7360
#define SB_OFF (SW_OFF + 24*32) // 8128
#define SMEM_F (SB_OFF + BT*NBETA) // 8768  (~35KB)

__global__ void __launch_bounds__(NTHR, 3) lbs_k(
    const float* __restrict__ vt,
    const float* __restrict__ sd,
    const float* __restrict__ pdirs,
    const float* __restrict__ wts,
    const float* __restrict__ betas,
    float* __restrict__ out)
{
    __shared__ __align__(16) float smem[SMEM_F];
    u32 sbase = (u32)__cvta_generic_to_shared(smem);

    int t = threadIdx.x;
    int vg = t & 7;           // 8 vert-groups of 4 verts
    int bg = t >> 3;          // 32 batch-groups of 2 batches (1 pair)
    int vbase = blockIdx.x * VT;
    int b0 = blockIdx.y * BT;
    bool tailv = (vbase + VT > V_NUM);

    // ---- group 0: weights + betas ----
    {
        for (int idx = t; idx < 24*32; idx += NTHR) {
            int j = idx >> 5, vv = idx & 31;
            int v = vbase + vv;
            cp4(sbase + (SW_OFF + idx)*4, (v < V_NUM) ? &wts[v*24 + j] : wts);
        }
        const float* bsrc = betas + (size_t)b0 * NBETA;
        for (int idx = t; idx < (BT*NBETA)/4; idx += NTHR)
            cp16(sbase + SB_OFF*4 + idx*16, bsrc + idx*4);
    }
    cp_commit();

    // ---- tile fill: pd as cp8 (handles ragged tail), pf as cp16 ----
    auto fill = [&](int buf, int kc) {
        u32 pdst = sbase + (buf*BUF_F)*4;
        const float* psrc = pdirs + (size_t)kc*VC + vbase*3;
        for (int idx = t; idx < PD_F/2; idx += NTHR) {
            int kk = idx / 48, r2 = idx - kk*48;
            const float* s = psrc + (size_t)kk*VC + r2*2;
            if (tailv && (vbase*3 + r2*2 + 2 > VC)) s = pdirs;
            cp8(pdst + (kk*96 + r2*2)*4, s);
        }
        u32 fdst = pdst + PD_F*4;
        const float* fsrc = g_pfT + (size_t)kc*B_NUM + b0;
        for (int idx = t; idx < PF_F/4; idx += NTHR) {
            int kk = idx >> 4, r = idx & 15;
            cp16(fdst + (kk*64 + r*4)*4, fsrc + (size_t)kk*B_NUM + r*4);
        }
    };

    fill(0, 0);      cp_commit();
    fill(1, KT);     cp_commit();

    ull vp2[2][6];    // [bb][vertex-pair element]  (thread: 4v x 2b)

    int kc = 0;
#pragma unroll 1
    for (int it = 0; it < NTILE; it++, kc += KT) {
        cp_wait<1>();
        __syncthreads();

        if (it == 0) {
            // shape blend init (betas in smem now)
            float f[2][12];
#pragma unroll
            for (int dv = 0; dv < 4; dv++) {
                int v = vbase + vg*4 + dv;
                float vt3[3], sdv[30];
                if (v < V_NUM) {
#pragma unroll
                    for (int c = 0; c < 3; c++) vt3[c] = vt[v*3+c];
                    const float2* s2 = (const float2*)&sd[v*30];
#pragma unroll
                    for (int i = 0; i < 15; i++) {
                        float2 d = s2[i];
                        sdv[2*i] = d.x; sdv[2*i+1] = d.y;
                    }
                } else {
#pragma unroll
                    for (int c = 0; c < 3; c++) vt3[c] = 0.f;
#pragma unroll
                    for (int i = 0; i < 30; i++) sdv[i] = 0.f;
                }
#pragma unroll
                for (int bb = 0; bb < 2; bb++) {
                    const float* bp = &smem[SB_OFF + (bg*2+bb)*NBETA];
                    float a0 = vt3[0], a1 = vt3[1], a2 = vt3[2];
#pragma unroll
                    for (int k = 0; k < NBETA; k++) {
                        float be = bp[k];
                        a0 += sdv[k]     * be;
                        a1 += sdv[10+k]  * be;
                        a2 += sdv[20+k]  * be;
                    }
                    f[bb][dv*3+0] = a0; f[bb][dv*3+1] = a1; f[bb][dv*3+2] = a2;
                }
            }
#pragma unroll
            for (int bb = 0; bb < 2; bb++)
#pragma unroll
                for (int e = 0; e < 6; e++)
                    vp2[bb][e] = pk(f[bb][2*e], f[bb][2*e+1]);
        }

        // compute this tile
        const float* pd = smem + (it & 1)*BUF_F;
        const float* pf = pd + PD_F;
#pragma unroll
        for (int kk = 0; kk < KT; kk++) {
            ull pfp = *(const ull*)&pf[kk*64 + bg*2];
            ull pp0 = pk(ulo(pfp), ulo(pfp));
            ull pp1 = pk(uhi(pfp), uhi(pfp));
            const ulonglong2* dp = (const ulonglong2*)&pd[kk*96 + vg*12];
            ulonglong2 d0 = dp[0], d1 = dp[1], d2 = dp[2];
            ull dd[6] = {d0.x, d0.y, d1.x, d1.y, d2.x, d2.y};
#pragma unroll
            for (int e = 0; e < 6; e++) {
                vp2[0][e] = ffma2(pp0, dd[e], vp2[0][e]);
                vp2[1][e] = ffma2(pp1, dd[e], vp2[1][e]);
            }
        }

        __syncthreads();
        if (it + 2 < NTILE) fill(it & 1, kc + 2*KT);
        cp_commit();   // possibly empty group (keeps wait numbering uniform)
    }

    // ---- phase 2: skinning blend; A from gmem (L2-resident), batch-pair packed ----
    // repack accumulators: vertex-pairs -> batch-pairs
    ull xp[12];
#pragma unroll
    for (int e = 0; e < 12; e++) {
        float fl = (e & 1) ? uhi(vp2[0][e>>1]) : ulo(vp2[0][e>>1]);
        float fh = (e & 1) ? uhi(vp2[1][e>>1]) : ulo(vp2[1][e>>1]);
        xp[e] = pk(fl, fh);
    }
    ull o2[12];
#pragma unroll
    for (int e = 0; e < 12; e++) o2[e] = pk(0.f, 0.f);

    const ulonglong2* Ab = (const ulonglong2*)(g_A2 + ((size_t)(b0 >> 1) + bg)*580);

#pragma unroll 2
    for (int j = 0; j < 24; j++) {
        float4 w4 = *(const float4*)&smem[SW_OFF + j*32 + vg*4];
        ull wp[4] = { pk(w4.x,w4.x), pk(w4.y,w4.y), pk(w4.z,w4.z), pk(w4.w,w4.w) };
#pragma unroll
        for (int r = 0; r < 3; r++) {
            ulonglong2 Ar0 = Ab[j*6 + r*2], Ar1 = Ab[j*6 + r*2 + 1];
            ull a0 = Ar0.x, a1 = Ar0.y, a2 = Ar1.x, a3 = Ar1.y;
#pragma unroll
            for (int dv = 0; dv < 4; dv++) {
                ull q = ffma2(a0, xp[dv*3+0],
                        ffma2(a1, xp[dv*3+1],
                        ffma2(a2, xp[dv*3+2], a3)));
                o2[dv*3+r] = ffma2(wp[dv], q, o2[dv*3+r]);
            }
        }
    }

    // ---- store: 2 batches x 12 contiguous floats (6 x float2 each) ----
    int v0 = vbase + vg*4;
    if (!tailv) {
#pragma unroll
        for (int s = 0; s < 2; s++) {
            int b = b0 + bg*2 + s;
            float* o = out + ((size_t)b*V_NUM + v0)*3;
#pragma unroll
            for (int k = 0; k < 6; k++) {
                float2 v2;
                v2.x = s ? uhi(o2[2*k])   : ulo(o2[2*k]);
                v2.y = s ? uhi(o2[2*k+1]) : ulo(o2[2*k+1]);
                *(float2*)(o + 2*k) = v2;
            }
        }
    } else {
#pragma unroll
        for (int s = 0; s < 2; s++) {
            int b = b0 + bg*2 + s;
#pragma unroll
            for (int e = 0; e < 12; e++) {
                int v = v0 + e/3;
                if (v < V_NUM) {
                    float val = s ? uhi(o2[e]) : ulo(o2[e]);
                    out[((size_t)b*V_NUM + v)*3 + (e % 3)] = val;
                }
            }
        }
    }
}

extern "C" void kernel_launch(void* const* d_in, const int* in_sizes, int n_in,
                              void* d_out, int out_size)
{
    const float* pose   = (const float*)d_in[0];
    const float* betas  = (const float*)d_in[1];
    const float* trans  = (const float*)d_in[2];
    const float* vt     = (const float*)d_in[3];
    const float* sd     = (const float*)d_in[4];
    const float* pdirs  = (const float*)d_in[5];
    const float* Jreg   = (const float*)d_in[6];
    const float* wts    = (const float*)d_in[7];
    // d_in[8] = parents (fixed SMPL topology, baked into __constant__)

    zero_k<<<1, 256>>>();
    regress_k<<<dim3(24, 14), 256>>>(Jreg, vt, sd);
    pose_k<<<B_NUM, 32>>>(pose, betas, trans);
    dim3 grid((V_NUM + VT - 1)/VT, B_NUM/BT);   // 216 x 8
    lbs_k<<<grid, NTHR>>>(vt, sd, pdirs, wts, betas, (float*)d_out);
}

// round 10
// speedup vs baseline: 1.7824x; 1.7824x over previous
#include <cuda_runtime.h>
#include <cuda_bf16.h>
#include <stdint.h>
#include <math.h>

#define V_NUM 6890
#define B_NUM 512
#define J_NUM 24
#define KP    207   // (J-1)*9
#define NBETA 10
#define VC    (V_NUM*3)   // 20670
#define KPAD  224         // K padded for 7 stages of 32
#define KTS   32          // k per stage
#define NSTG  7
#define NTHR  256

typedef unsigned long long ull;
typedef unsigned int u32;

__constant__ int c_par[24] = {-1,0,0,0,1,2,3,4,5,6,7,8,9,9,9,12,13,14,16,17,18,19,20,21};

// Scratch (no allocations allowed)
__device__ float g_Jt0[J_NUM*3];
__device__ float g_JS[J_NUM*3*NBETA];
__device__ __align__(16) float g_A2[(B_NUM/2)*580];            // batch-pair-interleaved affines
__device__ __align__(16) __nv_bfloat16 g_pfB[B_NUM*KPAD];      // pose_feature [b][k] bf16, zero-padded
__device__ __align__(16) __nv_bfloat16 g_pdB[(size_t)VC*KPAD]; // posedirs n-major [n][k] bf16 (9.3MB)

// ---- packed f32x2 helpers -------------------------------------------------
__device__ __forceinline__ ull pk(float l, float h) {
    ull r; asm("mov.b64 %0, {%1, %2};" : "=l"(r) : "f"(l), "f"(h)); return r;
}
__device__ __forceinline__ float ulo(ull v) {
    float l, h; asm("mov.b64 {%0, %1}, %2;" : "=f"(l), "=f"(h) : "l"(v)); return l;
}
__device__ __forceinline__ float uhi(ull v) {
    float l, h; asm("mov.b64 {%0, %1}, %2;" : "=f"(l), "=f"(h) : "l"(v)); return h;
}
__device__ __forceinline__ ull ffma2(ull a, ull b, ull c) {
    ull r; asm("fma.rn.f32x2 %0, %1, %2, %3;" : "=l"(r) : "l"(a), "l"(b), "l"(c)); return r;
}

// ---- cp.async helpers -----------------------------------------------------
__device__ __forceinline__ void cp16(u32 dst, const void* src) {
    asm volatile("cp.async.ca.shared.global [%0], [%1], 16;" :: "r"(dst), "l"(src));
}
__device__ __forceinline__ void cp4(u32 dst, const void* src) {
    asm volatile("cp.async.ca.shared.global [%0], [%1], 4;" :: "r"(dst), "l"(src));
}
__device__ __forceinline__ void cp_commit() { asm volatile("cp.async.commit_group;"); }
template<int N> __device__ __forceinline__ void cp_wait() {
    asm volatile("cp.async.wait_group %0;" :: "n"(N));
}

// ---- bf16 mma m16n8k16 ------------------------------------------------------
__device__ __forceinline__ void mma_bf16(float* d, const u32* a, u32 b0, u32 b1) {
    asm volatile(
        "mma.sync.aligned.m16n8k16.row.col.f32.bf16.bf16.f32 "
        "{%0,%1,%2,%3}, {%4,%5,%6,%7}, {%8,%9}, {%0,%1,%2,%3};"
        : "+f"(d[0]), "+f"(d[1]), "+f"(d[2]), "+f"(d[3])
        : "r"(a[0]), "r"(a[1]), "r"(a[2]), "r"(a[3]), "r"(b0), "r"(b1));
}

// ---------------------------------------------------------------------------
__global__ void zero_k()
{
    int t = threadIdx.x;
    if (t < J_NUM*3) g_Jt0[t] = 0.0f;
    for (int i = t; i < J_NUM*30; i += 256) g_JS[i] = 0.0f;
}

// ---------------------------------------------------------------------------
// cvtB_k: transpose + bf16-encode posedirs: g_pdB[n][k] = bf16(pdirs[k][n])
// 32x32 smem tile transpose, coalesced both sides.
// ---------------------------------------------------------------------------
__global__ void cvtB_k(const float* __restrict__ pdirs)
{
    __shared__ float tile[32][33];
    int n0 = blockIdx.x * 32;
    int k0 = blockIdx.y * 32;
    int t = threadIdx.x;   // 256
    int nn = t & 31, kq = t >> 5;
#pragma unroll
    for (int i = 0; i < 4; i++) {
        int kk = kq + i*8;
        int k = k0 + kk, n = n0 + nn;
        tile[kk][nn] = (k < KP && n < VC) ? pdirs[(size_t)k*VC + n] : 0.0f;
    }
    __syncthreads();
    int nn2 = t >> 3, q = t & 7;
    int n = n0 + nn2;
    if (n < VC) {
        __nv_bfloat162 p01 = __floats2bfloat162_rn(tile[q*4+0][nn2], tile[q*4+1][nn2]);
        __nv_bfloat162 p23 = __floats2bfloat162_rn(tile[q*4+2][nn2], tile[q*4+3][nn2]);
        __nv_bfloat162* dst = (__nv_bfloat162*)&g_pdB[(size_t)n*KPAD + k0 + q*4];
        dst[0] = p01;
        dst[1] = p23;
    }
}

// ---------------------------------------------------------------------------
__global__ void regress_k(const float* __restrict__ Jreg,
                          const float* __restrict__ vt,
                          const float* __restrict__ sd)
{
    int j = blockIdx.x;
    int chunk = blockIdx.y;
    const int CH = (V_NUM + 13) / 14;
    int v0 = chunk * CH;
    int v1 = min(v0 + CH, V_NUM);
    int t = threadIdx.x;
    int lane = t & 31, w = t >> 5;

    float acc[33];
#pragma unroll
    for (int i = 0; i < 33; i++) acc[i] = 0.f;
    for (int v = v0 + t; v < v1; v += 256) {
        float r = Jreg[j*V_NUM + v];
#pragma unroll
        for (int c = 0; c < 3; c++) acc[c] += r * vt[v*3+c];
#pragma unroll
        for (int i = 0; i < 30; i++) acc[3+i] += r * sd[v*30+i];
    }
    __shared__ float red[8][33];
#pragma unroll
    for (int i = 0; i < 33; i++) {
        float v = acc[i];
#pragma unroll
        for (int o = 16; o; o >>= 1) v += __shfl_xor_sync(0xffffffffu, v, o);
        if (lane == 0) red[w][i] = v;
    }
    __syncthreads();
    if (t < 33) {
        float s = 0.f;
#pragma unroll
        for (int ww = 0; ww < 8; ww++) s += red[ww][t];
        if (t < 3) atomicAdd(&g_Jt0[j*3 + t], s);
        else       atomicAdd(&g_JS[j*30 + (t-3)], s);
    }
}

// ---------------------------------------------------------------------------
__global__ void pose_k(const float* __restrict__ pose,
                       const float* __restrict__ betas,
                       const float* __restrict__ trans)
{
    int b = blockIdx.x;
    int lane = threadIdx.x;   // 32
    __shared__ float R[24][9];
    __shared__ float Jt[24][3];
    __shared__ float Tl[24][12];
    __shared__ float Tw[24][12];

    if (lane < 24) {
        float rx = pose[b*72 + lane*3 + 0];
        float ry = pose[b*72 + lane*3 + 1];
        float rz = pose[b*72 + lane*3 + 2];
        float ang = sqrtf(rx*rx + ry*ry + rz*rz + 1e-16f);
        float inv = 1.0f/ang;
        float ax = rx*inv, ay = ry*inv, az = rz*inv;
        float s = sinf(ang), c = cosf(ang), tt = 1.0f - c;
        R[lane][0] = c + tt*ax*ax;    R[lane][1] = tt*ax*ay - s*az; R[lane][2] = tt*ax*az + s*ay;
        R[lane][3] = tt*ax*ay + s*az; R[lane][4] = c + tt*ay*ay;    R[lane][5] = tt*ay*az - s*ax;
        R[lane][6] = tt*ax*az - s*ay; R[lane][7] = tt*ay*az + s*ax; R[lane][8] = c + tt*az*az;

        float bet[NBETA];
#pragma unroll
        for (int k = 0; k < NBETA; k++) bet[k] = betas[b*NBETA + k];
#pragma unroll
        for (int c3 = 0; c3 < 3; c3++) {
            float a = g_Jt0[lane*3 + c3];
#pragma unroll
            for (int k = 0; k < NBETA; k++) a += g_JS[lane*30 + c3*10 + k] * bet[k];
            Jt[lane][c3] = a;
        }
    }
    __syncwarp();

    // pose_feature row-major [b][k], bf16, zero-padded to KPAD
    for (int idx = lane; idx < KPAD; idx += 32) {
        float v = 0.0f;
        if (idx < KP) {
            int j = idx/9 + 1, e = idx%9;
            v = R[j][e] - ((e == 0 || e == 4 || e == 8) ? 1.0f : 0.0f);
        }
        g_pfB[b*KPAD + idx] = __float2bfloat16(v);
    }

    if (lane < 24) {
        float tx, ty, tz;
        if (lane == 0) { tx = Jt[0][0]; ty = Jt[0][1]; tz = Jt[0][2]; }
        else {
            int p = c_par[lane];
            tx = Jt[lane][0] - Jt[p][0];
            ty = Jt[lane][1] - Jt[p][1];
            tz = Jt[lane][2] - Jt[p][2];
        }
        Tl[lane][0] = R[lane][0]; Tl[lane][1] = R[lane][1]; Tl[lane][2]  = R[lane][2]; Tl[lane][3]  = tx;
        Tl[lane][4] = R[lane][3]; Tl[lane][5] = R[lane][4]; Tl[lane][6]  = R[lane][5]; Tl[lane][7]  = ty;
        Tl[lane][8] = R[lane][6]; Tl[lane][9] = R[lane][7]; Tl[lane][10] = R[lane][8]; Tl[lane][11] = tz;
    }
    __syncwarp();
    if (lane < 12) Tw[0][lane] = Tl[0][lane];
    __syncwarp();
    for (int i = 1; i < 24; i++) {
        if (lane < 12) {
            int r = lane >> 2, cc = lane & 3;
            int p = c_par[i];
            float v = Tw[p][r*4+0]*Tl[i][0+cc] + Tw[p][r*4+1]*Tl[i][4+cc] + Tw[p][r*4+2]*Tl[i][8+cc];
            if (cc == 3) v += Tw[p][r*4+3];
            Tw[i][lane] = v;
        }
        __syncwarp();
    }
    if (lane < 24) {
        float jx = Jt[lane][0], jy = Jt[lane][1], jz = Jt[lane][2];
        size_t base = (size_t)(b >> 1) * 580 + (b & 1);
#pragma unroll
        for (int r = 0; r < 3; r++) {
            float r0 = Tw[lane][r*4+0], r1 = Tw[lane][r*4+1], r2 = Tw[lane][r*4+2];
            float t3 = Tw[lane][r*4+3] - (r0*jx + r1*jy + r2*jz) + trans[b*3+r];
            int e = lane*12 + r*4;
            g_A2[base + (e+0)*2] = r0;
            g_A2[base + (e+1)*2] = r1;
            g_A2[base + (e+2)*2] = r2;
            g_A2[base + (e+3)*2] = t3;
        }
    }
}

// ---------------------------------------------------------------------------
// Main kernel: bf16 HMMA pose-blend GEMM + FFMA2 skinning.
// Block: 256 thr (8 warps = 4m x 2n). Tile: M=64 batches, N=96 v3 (32 verts).
// Stage buffers bf16, 80B pitch (conflict-free); Vp aliases them.
// ---------------------------------------------------------------------------
// byte offsets for bf16 stage buffers
#define AS_B   (64*80)            // 5120 B per A stage
#define BS_B   (96*80)            // 7680 B per B stage
#define AS0b   0
#define AS1b   AS_B
#define BS0b   (2*AS_B)           // 10240
#define BS1b   (BS0b + BS_B)      // 17920
#define STG_ENDb (BS1b + BS_B)    // 25600 B = 6400 floats
// float offsets
#define VP_OFF 0                  // aliased: Vp [64][100] = 6400 floats = 25600 B exactly
#define W_OFF  6400               // W [24][32]
#define BE_OFF (W_OFF + 24*32)    // 7168
#define SMEM_F (BE_OFF + 64*NBETA) // 7808 floats = 31232 B

__global__ void __launch_bounds__(NTHR, 3) lbs_k(
    const float* __restrict__ vt,
    const float* __restrict__ sd,
    const float* __restrict__ wts,
    const float* __restrict__ betas,
    float* __restrict__ out)
{
    __shared__ __align__(16) float smem[SMEM_F];
    u32 sbase = (u32)__cvta_generic_to_shared(smem);

    int t = threadIdx.x;
    int n0 = blockIdx.x * 96;          // v3 column base
    int vb = blockIdx.x * 32;          // vertex base
    int b0 = blockIdx.y * 64;          // batch base
    bool tailv = (vb + 32 > V_NUM);

    // ---- group 0: weights + betas + stage 0 ----
    for (int idx = t; idx < 24*32; idx += NTHR) {
        int j = idx >> 5, vv = idx & 31;
        int v = vb + vv;
        cp4(sbase + (W_OFF + idx)*4, (v < V_NUM) ? &wts[v*24 + j] : wts);
    }
    {
        const float* bsrc = betas + (size_t)b0 * NBETA;
        for (int idx = t; idx < (64*NBETA)/4; idx += NTHR)
            cp16(sbase + BE_OFF*4 + idx*16, bsrc + idx*4);
    }

    // ---- stage fill (bf16 tiles) ----
    auto fill = [&](int buf, int kc) {
        // A: pf [64 b][32 k] bf16 -> smem pitch 80B
        u32 adst = sbase + (buf ? AS1b : AS0b);
        const __nv_bfloat16* asrc = g_pfB + (size_t)b0*KPAD + kc;
        for (int idx = t; idx < 256; idx += NTHR) {
            int b = idx >> 2, q = idx & 3;
            cp16(adst + b*80 + q*16, asrc + (size_t)b*KPAD + q*8);
        }
        // B: g_pdB [96 n][32 k] bf16 -> smem pitch 80B (clamp OOB n-rows to row 0)
        u32 bdst = sbase + (buf ? BS1b : BS0b);
        for (int idx = t; idx < 384; idx += NTHR) {
            int n = idx >> 2, q = idx & 3;
            int gn = n0 + n;
            const __nv_bfloat16* s = g_pdB + (size_t)(gn < VC ? gn : 0)*KPAD + kc;
            cp16(bdst + n*80 + q*16, s + q*8);
        }
    };

    fill(0, 0);        cp_commit();   // group 0 (incl. W/betas)
    fill(1, KTS);      cp_commit();   // group 1

    // ---- GEMM: 7 stages x 2 k-steps, m16n8k16 bf16 ----
    int wid = t >> 5, lane = t & 31;
    int wm = wid & 3;          // 0..3 -> m offset wm*16
    int wn = wid >> 2;         // 0..1 -> n offset wn*48
    int gid = lane >> 2, tg = lane & 3;

    float d[6][4];
#pragma unroll
    for (int f = 0; f < 6; f++)
#pragma unroll
        for (int r = 0; r < 4; r++) d[f][r] = 0.0f;

#pragma unroll 1
    for (int it = 0; it < NSTG; it++) {
        cp_wait<1>();
        __syncthreads();

        const __nv_bfloat16* As = (const __nv_bfloat16*)((const char*)smem + (it & 1 ? AS1b : AS0b));
        const __nv_bfloat16* Bs = (const __nv_bfloat16*)((const char*)smem + (it & 1 ? BS1b : BS0b));
#pragma unroll
        for (int ks = 0; ks < 2; ks++) {
            u32 a[4];
            const __nv_bfloat16* ar = As + (wm*16 + gid)*40 + ks*16 + 2*tg;
            a[0] = *(const u32*)(ar);
            a[1] = *(const u32*)(ar + 8*40);
            a[2] = *(const u32*)(ar + 8);
            a[3] = *(const u32*)(ar + 8*40 + 8);
            const __nv_bfloat16* br = Bs + (wn*48 + gid)*40 + ks*16 + 2*tg;
#pragma unroll
            for (int f = 0; f < 6; f++) {
                u32 b0r = *(const u32*)(br + f*8*40);
                u32 b1r = *(const u32*)(br + f*8*40 + 8);
                mma_bf16(d[f], a, b0r, b1r);
            }
        }

        __syncthreads();
        if (it + 2 < NSTG) fill(it & 1, (it + 2)*KTS);
        cp_commit();
    }

    // ---- phase 2 mapping ----
    int vg = t & 7;            // 8 vert-groups of 4 verts
    int bg = t >> 3;           // 32 batch-pairs

    // shape blend (fp32)
    float f2[2][12];
    {
#pragma unroll
        for (int dv = 0; dv < 4; dv++) {
            int v = vb + vg*4 + dv;
            float vt3[3], sdv[30];
            if (v < V_NUM) {
#pragma unroll
                for (int c = 0; c < 3; c++) vt3[c] = vt[v*3+c];
                const float2* s2 = (const float2*)&sd[v*30];
#pragma unroll
                for (int i = 0; i < 15; i++) {
                    float2 dd = s2[i];
                    sdv[2*i] = dd.x; sdv[2*i+1] = dd.y;
                }
            } else {
#pragma unroll
                for (int c = 0; c < 3; c++) vt3[c] = 0.f;
#pragma unroll
                for (int i = 0; i < 30; i++) sdv[i] = 0.f;
            }
#pragma unroll
            for (int bb = 0; bb < 2; bb++) {
                const float* bp = &smem[BE_OFF + (bg*2+bb)*NBETA];
                float a0 = vt3[0], a1 = vt3[1], a2 = vt3[2];
#pragma unroll
                for (int k = 0; k < NBETA; k++) {
                    float be = bp[k];
                    a0 += sdv[k]    * be;
                    a1 += sdv[10+k] * be;
                    a2 += sdv[20+k] * be;
                }
                f2[bb][dv*3+0] = a0; f2[bb][dv*3+1] = a1; f2[bb][dv*3+2] = a2;
            }
        }
    }

    // ---- epilogue: D fragments -> Vp[64][100] (aliased over stage bufs) ----
    {
        float* Vp = smem + VP_OFF;
        int rb = wm*16 + gid;
#pragma unroll
        for (int f = 0; f < 6; f++) {
            int col = wn*48 + f*8 + 2*tg;
            *(float2*)&Vp[rb*100 + col]     = make_float2(d[f][0], d[f][1]);
            *(float2*)&Vp[(rb+8)*100 + col] = make_float2(d[f][2], d[f][3]);
        }
    }
    __syncthreads();

    // ---- pack accumulators over batch pair ----
    ull xp[12];
    {
        const float* VL = &smem[VP_OFF + (bg*2)*100 + vg*12];
        const float* VH = VL + 100;
        float4 L0 = *(const float4*)&VL[0], L1 = *(const float4*)&VL[4], L2 = *(const float4*)&VL[8];
        float4 H0 = *(const float4*)&VH[0], H1 = *(const float4*)&VH[4], H2 = *(const float4*)&VH[8];
        float L[12] = {L0.x,L0.y,L0.z,L0.w, L1.x,L1.y,L1.z,L1.w, L2.x,L2.y,L2.z,L2.w};
        float H[12] = {H0.x,H0.y,H0.z,H0.w, H1.x,H1.y,H1.z,H1.w, H2.x,H2.y,H2.z,H2.w};
#pragma unroll
        for (int e = 0; e < 12; e++)
            xp[e] = pk(f2[0][e] + L[e], f2[1][e] + H[e]);
    }

    // ---- skinning blend (A from L2-resident gmem) ----
    ull o2[12];
#pragma unroll
    for (int e = 0; e < 12; e++) o2[e] = pk(0.f, 0.f);

    const ulonglong2* Ab = (const ulonglong2*)(g_A2 + ((size_t)(b0 >> 1) + bg)*580);

#pragma unroll 2
    for (int j = 0; j < 24; j++) {
        float4 w4 = *(const float4*)&smem[W_OFF + j*32 + vg*4];
        ull wp[4] = { pk(w4.x,w4.x), pk(w4.y,w4.y), pk(w4.z,w4.z), pk(w4.w,w4.w) };
#pragma unroll
        for (int r = 0; r < 3; r++) {
            ulonglong2 Ar0 = Ab[j*6 + r*2], Ar1 = Ab[j*6 + r*2 + 1];
            ull a0 = Ar0.x, a1 = Ar0.y, a2 = Ar1.x, a3 = Ar1.y;
#pragma unroll
            for (int dv = 0; dv < 4; dv++) {
                ull q = ffma2(a0, xp[dv*3+0],
                        ffma2(a1, xp[dv*3+1],
                        ffma2(a2, xp[dv*3+2], a3)));
                o2[dv*3+r] = ffma2(wp[dv], q, o2[dv*3+r]);
            }
        }
    }

    // ---- store ----
    int v0 = vb + vg*4;
    if (!tailv) {
#pragma unroll
        for (int s = 0; s < 2; s++) {
            int b = b0 + bg*2 + s;
            float* o = out + ((size_t)b*V_NUM + v0)*3;
#pragma unroll
            for (int k = 0; k < 6; k++) {
                float2 v2;
                v2.x = s ? uhi(o2[2*k])   : ulo(o2[2*k]);
                v2.y = s ? uhi(o2[2*k+1]) : ulo(o2[2*k+1]);
                *(float2*)(o + 2*k) = v2;
            }
        }
    } else {
#pragma unroll
        for (int s = 0; s < 2; s++) {
            int b = b0 + bg*2 + s;
#pragma unroll
            for (int e = 0; e < 12; e++) {
                int v = v0 + e/3;
                if (v < V_NUM) {
                    float val = s ? uhi(o2[e]) : ulo(o2[e]);
                    out[((size_t)b*V_NUM + v)*3 + (e % 3)] = val;
                }
            }
        }
    }
}

extern "C" void kernel_launch(void* const* d_in, const int* in_sizes, int n_in,
                              void* d_out, int out_size)
{
    const float* pose   = (const float*)d_in[0];
    const float* betas  = (const float*)d_in[1];
    const float* trans  = (const float*)d_in[2];
    const float* vt     = (const float*)d_in[3];
    const float* sd     = (const float*)d_in[4];
    const float* pdirs  = (const float*)d_in[5];
    const float* Jreg   = (const float*)d_in[6];
    const float* wts    = (const float*)d_in[7];
    // d_in[8] = parents (fixed SMPL topology, baked into __constant__)

    zero_k<<<1, 256>>>();
    cvtB_k<<<dim3((VC + 31)/32, KPAD/32), 256>>>(pdirs);   // 646 x 7
    regress_k<<<dim3(24, 14), 256>>>(Jreg, vt, sd);
    pose_k<<<B_NUM, 32>>>(pose, betas, trans);
    dim3 grid((VC + 95)/96, B_NUM/64);   // 216 x 8
    lbs_k<<<grid, NTHR>>>(vt, sd, wts, betas, (float*)d_out);
}

// round 11
// speedup vs baseline: 1.8322x; 1.0280x over previous
#include <cuda_runtime.h>
#include <cuda_bf16.h>
#include <stdint.h>
#include <math.h>

#define V_NUM 6890
#define B_NUM 512
#define J_NUM 24
#define KP    207   // (J-1)*9
#define NBETA 10
#define VC    (V_NUM*3)   // 20670
#define KPAD  224         // K padded for 7 stages of 32
#define KTS   32          // k per stage
#define NSTG  7
#define NTHR  256

typedef unsigned long long ull;
typedef unsigned int u32;

__constant__ int c_par[24] = {-1,0,0,0,1,2,3,4,5,6,7,8,9,9,9,12,13,14,16,17,18,19,20,21};

// Scratch (no allocations allowed)
__device__ float g_Jt0[J_NUM*3];
__device__ float g_JS[J_NUM*3*NBETA];
__device__ __align__(16) float g_A2[(B_NUM/2)*580];            // batch-pair-interleaved affines
__device__ __align__(16) __nv_bfloat16 g_pfB[B_NUM*KPAD];      // pose_feature [b][k] bf16, zero-padded
__device__ __align__(16) __nv_bfloat16 g_pdB[(size_t)VC*KPAD]; // posedirs n-major [n][k] bf16 (9.3MB)

// ---- packed f32x2 helpers -------------------------------------------------
__device__ __forceinline__ ull pk(float l, float h) {
    ull r; asm("mov.b64 %0, {%1, %2};" : "=l"(r) : "f"(l), "f"(h)); return r;
}
__device__ __forceinline__ float ulo(ull v) {
    float l, h; asm("mov.b64 {%0, %1}, %2;" : "=f"(l), "=f"(h) : "l"(v)); return l;
}
__device__ __forceinline__ float uhi(ull v) {
    float l, h; asm("mov.b64 {%0, %1}, %2;" : "=f"(l), "=f"(h) : "l"(v)); return h;
}
__device__ __forceinline__ ull ffma2(ull a, ull b, ull c) {
    ull r; asm("fma.rn.f32x2 %0, %1, %2, %3;" : "=l"(r) : "l"(a), "l"(b), "l"(c)); return r;
}

// ---- cp.async helpers -----------------------------------------------------
__device__ __forceinline__ void cp16(u32 dst, const void* src) {
    asm volatile("cp.async.ca.shared.global [%0], [%1], 16;" :: "r"(dst), "l"(src));
}
__device__ __forceinline__ void cp4(u32 dst, const void* src) {
    asm volatile("cp.async.ca.shared.global [%0], [%1], 4;" :: "r"(dst), "l"(src));
}
__device__ __forceinline__ void cp_commit() { asm volatile("cp.async.commit_group;"); }
template<int N> __device__ __forceinline__ void cp_wait() {
    asm volatile("cp.async.wait_group %0;" :: "n"(N));
}

// ---- bf16 mma m16n8k16 ------------------------------------------------------
__device__ __forceinline__ void mma_bf16(float* d, const u32* a, u32 b0, u32 b1) {
    asm volatile(
        "mma.sync.aligned.m16n8k16.row.col.f32.bf16.bf16.f32 "
        "{%0,%1,%2,%3}, {%4,%5,%6,%7}, {%8,%9}, {%0,%1,%2,%3};"
        : "+f"(d[0]), "+f"(d[1]), "+f"(d[2]), "+f"(d[3])
        : "r"(a[0]), "r"(a[1]), "r"(a[2]), "r"(a[3]), "r"(b0), "r"(b1));
}

// ---------------------------------------------------------------------------
// cvtB_k: transpose + bf16-encode posedirs: g_pdB[n][k] = bf16(pdirs[k][n]).
// Block (0,0) additionally zeroes the regress accumulators (same-stream
// ordering guarantees completion before regress_k starts).
// ---------------------------------------------------------------------------
__global__ void cvtB_k(const float* __restrict__ pdirs)
{
    __shared__ float tile[32][33];
    int t = threadIdx.x;   // 256
    if (blockIdx.x == 0 && blockIdx.y == 0) {
        if (t < J_NUM*3) g_Jt0[t] = 0.0f;
        for (int i = t; i < J_NUM*30; i += 256) g_JS[i] = 0.0f;
    }
    int n0 = blockIdx.x * 32;
    int k0 = blockIdx.y * 32;
    int nn = t & 31, kq = t >> 5;
#pragma unroll
    for (int i = 0; i < 4; i++) {
        int kk = kq + i*8;
        int k = k0 + kk, n = n0 + nn;
        tile[kk][nn] = (k < KP && n < VC) ? pdirs[(size_t)k*VC + n] : 0.0f;
    }
    __syncthreads();
    int nn2 = t >> 3, q = t & 7;
    int n = n0 + nn2;
    if (n < VC) {
        __nv_bfloat162 p01 = __floats2bfloat162_rn(tile[q*4+0][nn2], tile[q*4+1][nn2]);
        __nv_bfloat162 p23 = __floats2bfloat162_rn(tile[q*4+2][nn2], tile[q*4+3][nn2]);
        __nv_bfloat162* dst = (__nv_bfloat162*)&g_pdB[(size_t)n*KPAD + k0 + q*4];
        dst[0] = p01;
        dst[1] = p23;
    }
}

// ---------------------------------------------------------------------------
__global__ void regress_k(const float* __restrict__ Jreg,
                          const float* __restrict__ vt,
                          const float* __restrict__ sd)
{
    int j = blockIdx.x;
    int chunk = blockIdx.y;
    const int CH = (V_NUM + 13) / 14;
    int v0 = chunk * CH;
    int v1 = min(v0 + CH, V_NUM);
    int t = threadIdx.x;
    int lane = t & 31, w = t >> 5;

    float acc[33];
#pragma unroll
    for (int i = 0; i < 33; i++) acc[i] = 0.f;
    for (int v = v0 + t; v < v1; v += 256) {
        float r = Jreg[j*V_NUM + v];
#pragma unroll
        for (int c = 0; c < 3; c++) acc[c] += r * vt[v*3+c];
#pragma unroll
        for (int i = 0; i < 30; i++) acc[3+i] += r * sd[v*30+i];
    }
    __shared__ float red[8][33];
#pragma unroll
    for (int i = 0; i < 33; i++) {
        float v = acc[i];
#pragma unroll
        for (int o = 16; o; o >>= 1) v += __shfl_xor_sync(0xffffffffu, v, o);
        if (lane == 0) red[w][i] = v;
    }
    __syncthreads();
    if (t < 33) {
        float s = 0.f;
#pragma unroll
        for (int ww = 0; ww < 8; ww++) s += red[ww][t];
        if (t < 3) atomicAdd(&g_Jt0[j*3 + t], s);
        else       atomicAdd(&g_JS[j*30 + (t-3)], s);
    }
}

// ---------------------------------------------------------------------------
// pose_k: 8 batches per block (one warp each).
// ---------------------------------------------------------------------------
__global__ void pose_k(const float* __restrict__ pose,
                       const float* __restrict__ betas,
                       const float* __restrict__ trans)
{
    int warp = threadIdx.x >> 5;
    int lane = threadIdx.x & 31;
    int b = blockIdx.x*8 + warp;
    __shared__ float R[8][24][9];
    __shared__ float Jt[8][24][3];
    __shared__ float Tl[8][24][12];
    __shared__ float Tw[8][24][12];

    if (lane < 24) {
        float rx = pose[b*72 + lane*3 + 0];
        float ry = pose[b*72 + lane*3 + 1];
        float rz = pose[b*72 + lane*3 + 2];
        float ang = sqrtf(rx*rx + ry*ry + rz*rz + 1e-16f);
        float inv = 1.0f/ang;
        float ax = rx*inv, ay = ry*inv, az = rz*inv;
        float s = sinf(ang), c = cosf(ang), tt = 1.0f - c;
        R[warp][lane][0] = c + tt*ax*ax;    R[warp][lane][1] = tt*ax*ay - s*az; R[warp][lane][2] = tt*ax*az + s*ay;
        R[warp][lane][3] = tt*ax*ay + s*az; R[warp][lane][4] = c + tt*ay*ay;    R[warp][lane][5] = tt*ay*az - s*ax;
        R[warp][lane][6] = tt*ax*az - s*ay; R[warp][lane][7] = tt*ay*az + s*ax; R[warp][lane][8] = c + tt*az*az;

        float bet[NBETA];
#pragma unroll
        for (int k = 0; k < NBETA; k++) bet[k] = betas[b*NBETA + k];
#pragma unroll
        for (int c3 = 0; c3 < 3; c3++) {
            float a = g_Jt0[lane*3 + c3];
#pragma unroll
            for (int k = 0; k < NBETA; k++) a += g_JS[lane*30 + c3*10 + k] * bet[k];
            Jt[warp][lane][c3] = a;
        }
    }
    __syncwarp();

    // pose_feature row-major [b][k], bf16, zero-padded to KPAD
    for (int idx = lane; idx < KPAD; idx += 32) {
        float v = 0.0f;
        if (idx < KP) {
            int j = idx/9 + 1, e = idx%9;
            v = R[warp][j][e] - ((e == 0 || e == 4 || e == 8) ? 1.0f : 0.0f);
        }
        g_pfB[b*KPAD + idx] = __float2bfloat16(v);
    }

    if (lane < 24) {
        float tx, ty, tz;
        if (lane == 0) { tx = Jt[warp][0][0]; ty = Jt[warp][0][1]; tz = Jt[warp][0][2]; }
        else {
            int p = c_par[lane];
            tx = Jt[warp][lane][0] - Jt[warp][p][0];
            ty = Jt[warp][lane][1] - Jt[warp][p][1];
            tz = Jt[warp][lane][2] - Jt[warp][p][2];
        }
        Tl[warp][lane][0] = R[warp][lane][0]; Tl[warp][lane][1] = R[warp][lane][1]; Tl[warp][lane][2]  = R[warp][lane][2]; Tl[warp][lane][3]  = tx;
        Tl[warp][lane][4] = R[warp][lane][3]; Tl[warp][lane][5] = R[warp][lane][4]; Tl[warp][lane][6]  = R[warp][lane][5]; Tl[warp][lane][7]  = ty;
        Tl[warp][lane][8] = R[warp][lane][6]; Tl[warp][lane][9] = R[warp][lane][7]; Tl[warp][lane][10] = R[warp][lane][8]; Tl[warp][lane][11] = tz;
    }
    __syncwarp();
    if (lane < 12) Tw[warp][0][lane] = Tl[warp][0][lane];
    __syncwarp();
    for (int i = 1; i < 24; i++) {
        if (lane < 12) {
            int r = lane >> 2, cc = lane & 3;
            int p = c_par[i];
            float v = Tw[warp][p][r*4+0]*Tl[warp][i][0+cc] + Tw[warp][p][r*4+1]*Tl[warp][i][4+cc] + Tw[warp][p][r*4+2]*Tl[warp][i][8+cc];
            if (cc == 3) v += Tw[warp][p][r*4+3];
            Tw[warp][i][lane] = v;
        }
        __syncwarp();
    }
    if (lane < 24) {
        float jx = Jt[warp][lane][0], jy = Jt[warp][lane][1], jz = Jt[warp][lane][2];
        size_t base = (size_t)(b >> 1) * 580 + (b & 1);
#pragma unroll
        for (int r = 0; r < 3; r++) {
            float r0 = Tw[warp][lane][r*4+0], r1 = Tw[warp][lane][r*4+1], r2 = Tw[warp][lane][r*4+2];
            float t3 = Tw[warp][lane][r*4+3] - (r0*jx + r1*jy + r2*jz) + trans[b*3+r];
            int e = lane*12 + r*4;
            g_A2[base + (e+0)*2] = r0;
            g_A2[base + (e+1)*2] = r1;
            g_A2[base + (e+2)*2] = r2;
            g_A2[base + (e+3)*2] = t3;
        }
    }
}

// ---------------------------------------------------------------------------
// Main kernel: bf16 HMMA pose-blend GEMM (3-stage cp.async ring) + FFMA2 skinning.
// Block: 256 thr (8 warps = 4m x 2n). Tile: M=64 batches, N=96 v3 (32 verts).
// ---------------------------------------------------------------------------
// byte offsets for bf16 stage buffers (3-stage ring)
#define AS_B   (64*80)            // 5120 B per A stage
#define BS_B   (96*80)            // 7680 B per B stage
#define AS0b   0                  // A stages at 0, 5120, 10240
#define BS0b   (3*AS_B)           // B stages at 15360, 23040, 30720
#define STG_ENDb (BS0b + 3*BS_B)  // 38400 B = 9600 floats
// float offsets
#define VP_OFF 0                  // aliased: Vp [64][100] = 25600 B <= 38400 B
#define W_OFF  9600               // W [24][32]
#define BE_OFF (W_OFF + 24*32)    // 10368
#define SMEM_F (BE_OFF + 64*NBETA) // 11008 floats = 44032 B (static)

__global__ void __launch_bounds__(NTHR, 3) lbs_k(
    const float* __restrict__ vt,
    const float* __restrict__ sd,
    const float* __restrict__ wts,
    const float* __restrict__ betas,
    float* __restrict__ out)
{
    __shared__ __align__(16) float smem[SMEM_F];
    u32 sbase = (u32)__cvta_generic_to_shared(smem);

    int t = threadIdx.x;
    int vb = blockIdx.x * 32;          // vertex base
    int n0 = blockIdx.x * 96;          // v3 column base
    int b0 = blockIdx.y * 64;          // batch base
    bool tailv = (vb + 32 > V_NUM);

    // ---- group 0: weights + betas + stage 0 ----
    for (int idx = t; idx < 24*32; idx += NTHR) {
        int j = idx >> 5, vv = idx & 31;
        int v = vb + vv;
        cp4(sbase + (W_OFF + idx)*4, (v < V_NUM) ? &wts[v*24 + j] : wts);
    }
    {
        const float* bsrc = betas + (size_t)b0 * NBETA;
        for (int idx = t; idx < (64*NBETA)/4; idx += NTHR)
            cp16(sbase + BE_OFF*4 + idx*16, bsrc + idx*4);
    }

    // ---- stage fill (bf16 tiles, 3-stage ring) ----
    auto fill = [&](int buf, int kc) {
        // A: pf [64 b][32 k] bf16 -> smem pitch 80B
        u32 adst = sbase + AS0b + buf*AS_B;
        const __nv_bfloat16* asrc = g_pfB + (size_t)b0*KPAD + kc;
        for (int idx = t; idx < 256; idx += NTHR) {
            int b = idx >> 2, q = idx & 3;
            cp16(adst + b*80 + q*16, asrc + (size_t)b*KPAD + q*8);
        }
        // B: g_pdB [96 n][32 k] bf16 -> smem pitch 80B (clamp OOB n-rows to row 0)
        u32 bdst = sbase + BS0b + buf*BS_B;
        for (int idx = t; idx < 384; idx += NTHR) {
            int n = idx >> 2, q = idx & 3;
            int gn = n0 + n;
            const __nv_bfloat16* s = g_pdB + (size_t)(gn < VC ? gn : 0)*KPAD + kc;
            cp16(bdst + n*80 + q*16, s + q*8);
        }
    };

    fill(0, 0);        cp_commit();   // G0 (incl. W/betas)
    fill(1, KTS);      cp_commit();   // G1

    // ---- GEMM: 7 stages x 2 k-steps, m16n8k16 bf16 ----
    int wid = t >> 5, lane = t & 31;
    int wm = wid & 3;          // 0..3 -> m offset wm*16
    int wn = wid >> 2;         // 0..1 -> n offset wn*48
    int gid = lane >> 2, tg = lane & 3;

    float d[6][4];
#pragma unroll
    for (int f = 0; f < 6; f++)
#pragma unroll
        for (int r = 0; r < 4; r++) d[f][r] = 0.0f;

#pragma unroll 1
    for (int it = 0; it < NSTG; it++) {
        cp_wait<1>();
        __syncthreads();

        int buf = it % 3;
        const __nv_bfloat16* As = (const __nv_bfloat16*)((const char*)smem + AS0b + buf*AS_B);
        const __nv_bfloat16* Bs = (const __nv_bfloat16*)((const char*)smem + BS0b + buf*BS_B);
#pragma unroll
        for (int ks = 0; ks < 2; ks++) {
            u32 a[4];
            const __nv_bfloat16* ar = As + (wm*16 + gid)*40 + ks*16 + 2*tg;
            a[0] = *(const u32*)(ar);
            a[1] = *(const u32*)(ar + 8*40);
            a[2] = *(const u32*)(ar + 8);
            a[3] = *(const u32*)(ar + 8*40 + 8);
            const __nv_bfloat16* br = Bs + (wn*48 + gid)*40 + ks*16 + 2*tg;
#pragma unroll
            for (int f = 0; f < 6; f++) {
                u32 b0r = *(const u32*)(br + f*8*40);
                u32 b1r = *(const u32*)(br + f*8*40 + 8);
                mma_bf16(d[f], a, b0r, b1r);
            }
        }

        // Refill the buffer consumed at it-1 (ordered by this iteration's barrier).
        if (it + 2 < NSTG) fill((it + 2) % 3, (it + 2)*KTS);
        cp_commit();
    }
    __syncthreads();   // all compute done before Vp aliases the stage buffers

    // ---- phase 2 mapping ----
    int vg = t & 7;            // 8 vert-groups of 4 verts
    int bg = t >> 3;           // 32 batch-pairs

    // shape blend (fp32)
    float f2[2][12];
    {
#pragma unroll
        for (int dv = 0; dv < 4; dv++) {
            int v = vb + vg*4 + dv;
            float vt3[3], sdv[30];
            if (v < V_NUM) {
#pragma unroll
                for (int c = 0; c < 3; c++) vt3[c] = vt[v*3+c];
                const float2* s2 = (const float2*)&sd[v*30];
#pragma unroll
                for (int i = 0; i < 15; i++) {
                    float2 dd = s2[i];
                    sdv[2*i] = dd.x; sdv[2*i+1] = dd.y;
                }
            } else {
#pragma unroll
                for (int c = 0; c < 3; c++) vt3[c] = 0.f;
#pragma unroll
                for (int i = 0; i < 30; i++) sdv[i] = 0.f;
            }
#pragma unroll
            for (int bb = 0; bb < 2; bb++) {
                const float* bp = &smem[BE_OFF + (bg*2+bb)*NBETA];
                float a0 = vt3[0], a1 = vt3[1], a2 = vt3[2];
#pragma unroll
                for (int k = 0; k < NBETA; k++) {
                    float be = bp[k];
                    a0 += sdv[k]    * be;
                    a1 += sdv[10+k] * be;
                    a2 += sdv[20+k] * be;
                }
                f2[bb][dv*3+0] = a0; f2[bb][dv*3+1] = a1; f2[bb][dv*3+2] = a2;
            }
        }
    }

    // ---- epilogue: D fragments -> Vp[64][100] (aliased over stage bufs) ----
    {
        float* Vp = smem + VP_OFF;
        int rb = wm*16 + gid;
#pragma unroll
        for (int f = 0; f < 6; f++) {
            int col = wn*48 + f*8 + 2*tg;
            *(float2*)&Vp[rb*100 + col]     = make_float2(d[f][0], d[f][1]);
            *(float2*)&Vp[(rb+8)*100 + col] = make_float2(d[f][2], d[f][3]);
        }
    }
    __syncthreads();

    // ---- pack accumulators over batch pair ----
    ull xp[12];
    {
        const float* VL = &smem[VP_OFF + (bg*2)*100 + vg*12];
        const float* VH = VL + 100;
        float4 L0 = *(const float4*)&VL[0], L1 = *(const float4*)&VL[4], L2 = *(const float4*)&VL[8];
        float4 H0 = *(const float4*)&VH[0], H1 = *(const float4*)&VH[4], H2 = *(const float4*)&VH[8];
        float L[12] = {L0.x,L0.y,L0.z,L0.w, L1.x,L1.y,L1.z,L1.w, L2.x,L2.y,L2.z,L2.w};
        float H[12] = {H0.x,H0.y,H0.z,H0.w, H1.x,H1.y,H1.z,H1.w, H2.x,H2.y,H2.z,H2.w};
#pragma unroll
        for (int e = 0; e < 12; e++)
            xp[e] = pk(f2[0][e] + L[e], f2[1][e] + H[e]);
    }

    // ---- skinning blend (A from L2-resident gmem) ----
    ull o2[12];
#pragma unroll
    for (int e = 0; e < 12; e++) o2[e] = pk(0.f, 0.f);

    const ulonglong2* Ab = (const ulonglong2*)(g_A2 + ((size_t)(b0 >> 1) + bg)*580);

#pragma unroll 2
    for (int j = 0; j < 24; j++) {
        float4 w4 = *(const float4*)&smem[W_OFF + j*32 + vg*4];
        ull wp[4] = { pk(w4.x,w4.x), pk(w4.y,w4.y), pk(w4.z,w4.z), pk(w4.w,w4.w) };
#pragma unroll
        for (int r = 0; r < 3; r++) {
            ulonglong2 Ar0 = Ab[j*6 + r*2], Ar1 = Ab[j*6 + r*2 + 1];
            ull a0 = Ar0.x, a1 = Ar0.y, a2 = Ar1.x, a3 = Ar1.y;
#pragma unroll
            for (int dv = 0; dv < 4; dv++) {
                ull q = ffma2(a0, xp[dv*3+0],
                        ffma2(a1, xp[dv*3+1],
                        ffma2(a2, xp[dv*3+2], a3)));
                o2[dv*3+r] = ffma2(wp[dv], q, o2[dv*3+r]);
            }
        }
    }

    // ---- store ----
    int v0 = vb + vg*4;
    if (!tailv) {
#pragma unroll
        for (int s = 0; s < 2; s++) {
            int b = b0 + bg*2 + s;
            float* o = out + ((size_t)b*V_NUM + v0)*3;
#pragma unroll
            for (int k = 0; k < 6; k++) {
                float2 v2;
                v2.x = s ? uhi(o2[2*k])   : ulo(o2[2*k]);
                v2.y = s ? uhi(o2[2*k+1]) : ulo(o2[2*k+1]);
                *(float2*)(o + 2*k) = v2;
            }
        }
    } else {
#pragma unroll
        for (int s = 0; s < 2; s++) {
            int b = b0 + bg*2 + s;
#pragma unroll
            for (int e = 0; e < 12; e++) {
                int v = v0 + e/3;
                if (v < V_NUM) {
                    float val = s ? uhi(o2[e]) : ulo(o2[e]);
                    out[((size_t)b*V_NUM + v)*3 + (e % 3)] = val;
                }
            }
        }
    }
}

extern "C" void kernel_launch(void* const* d_in, const int* in_sizes, int n_in,
                              void* d_out, int out_size)
{
    const float* pose   = (const float*)d_in[0];
    const float* betas  = (const float*)d_in[1];
    const float* trans  = (const float*)d_in[2];
    const float* vt     = (const float*)d_in[3];
    const float* sd     = (const float*)d_in[4];
    const float* pdirs  = (const float*)d_in[5];
    const float* Jreg   = (const float*)d_in[6];
    const float* wts    = (const float*)d_in[7];
    // d_in[8] = parents (fixed SMPL topology, baked into __constant__)

    cvtB_k<<<dim3((VC + 31)/32, KPAD/32), 256>>>(pdirs);   // 646 x 7 (also zeroes accums)
    regress_k<<<dim3(24, 14), 256>>>(Jreg, vt, sd);
    pose_k<<<B_NUM/8, 256>>>(pose, betas, trans);
    dim3 grid((VC + 95)/96, B_NUM/64);   // 216 x 8
    lbs_k<<<grid, NTHR>>>(vt, sd, wts, betas, (float*)d_out);
}

// round 13
// speedup vs baseline: 1.8628x; 1.0167x over previous
#include <cuda_runtime.h>
#include <cuda_bf16.h>
#include <stdint.h>
#include <math.h>

#define V_NUM 6890
#define B_NUM 512
#define J_NUM 24
#define KP    207   // (J-1)*9
#define NBETA 10
#define VC    (V_NUM*3)   // 20670
#define KPAD  224         // K padded for 7 stages of 32
#define KTS   32          // k per stage
#define NSTG  7
#define NTHR  256

typedef unsigned long long ull;
typedef unsigned int u32;

__constant__ int c_par[24] = {-1,0,0,0,1,2,3,4,5,6,7,8,9,9,9,12,13,14,16,17,18,19,20,21};

// Scratch (no allocations allowed)
__device__ float g_Jt0[J_NUM*3];
__device__ float g_JS[J_NUM*3*NBETA];
__device__ __align__(16) float g_A2[(B_NUM/2)*580];            // batch-pair-interleaved affines
__device__ __align__(16) __nv_bfloat16 g_pfB[B_NUM*KPAD];      // pose_feature [b][k] bf16, zero-padded
__device__ __align__(16) __nv_bfloat16 g_pdB[(size_t)VC*KPAD]; // posedirs n-major [n][k] bf16 (9.3MB)

// ---- packed f32x2 helpers -------------------------------------------------
__device__ __forceinline__ ull pk(float l, float h) {
    ull r; asm("mov.b64 %0, {%1, %2};" : "=l"(r) : "f"(l), "f"(h)); return r;
}
__device__ __forceinline__ float ulo(ull v) {
    float l, h; asm("mov.b64 {%0, %1}, %2;" : "=f"(l), "=f"(h) : "l"(v)); return l;
}
__device__ __forceinline__ float uhi(ull v) {
    float l, h; asm("mov.b64 {%0, %1}, %2;" : "=f"(l), "=f"(h) : "l"(v)); return h;
}
__device__ __forceinline__ ull ffma2(ull a, ull b, ull c) {
    ull r; asm("fma.rn.f32x2 %0, %1, %2, %3;" : "=l"(r) : "l"(a), "l"(b), "l"(c)); return r;
}

// ---- cp.async helpers -----------------------------------------------------
__device__ __forceinline__ void cp16(u32 dst, const void* src) {
    asm volatile("cp.async.ca.shared.global [%0], [%1], 16;" :: "r"(dst), "l"(src));
}
__device__ __forceinline__ void cp4(u32 dst, const void* src) {
    asm volatile("cp.async.ca.shared.global [%0], [%1], 4;" :: "r"(dst), "l"(src));
}
__device__ __forceinline__ void cp_commit() { asm volatile("cp.async.commit_group;"); }
template<int N> __device__ __forceinline__ void cp_wait() {
    asm volatile("cp.async.wait_group %0;" :: "n"(N));
}

// ---- ldmatrix + bf16 mma ----------------------------------------------------
__device__ __forceinline__ void ldsm4(u32& r0, u32& r1, u32& r2, u32& r3, u32 addr) {
    asm volatile("ldmatrix.sync.aligned.m8n8.x4.shared.b16 {%0,%1,%2,%3}, [%4];"
        : "=r"(r0), "=r"(r1), "=r"(r2), "=r"(r3) : "r"(addr));
}
__device__ __forceinline__ void mma_bf16(float* d, const u32* a, u32 b0, u32 b1) {
    asm volatile(
        "mma.sync.aligned.m16n8k16.row.col.f32.bf16.bf16.f32 "
        "{%0,%1,%2,%3}, {%4,%5,%6,%7}, {%8,%9}, {%0,%1,%2,%3};"
        : "+f"(d[0]), "+f"(d[1]), "+f"(d[2]), "+f"(d[3])
        : "r"(a[0]), "r"(a[1]), "r"(a[2]), "r"(a[3]), "r"(b0), "r"(b1));
}

// ---------------------------------------------------------------------------
// cvtB_k: transpose + bf16-encode posedirs; block (0,0) zeroes accumulators.
// ---------------------------------------------------------------------------
__global__ void cvtB_k(const float* __restrict__ pdirs)
{
    __shared__ float tile[32][33];
    int t = threadIdx.x;   // 256
    if (blockIdx.x == 0 && blockIdx.y == 0) {
        if (t < J_NUM*3) g_Jt0[t] = 0.0f;
        for (int i = t; i < J_NUM*30; i += 256) g_JS[i] = 0.0f;
    }
    int n0 = blockIdx.x * 32;
    int k0 = blockIdx.y * 32;
    int nn = t & 31, kq = t >> 5;
#pragma unroll
    for (int i = 0; i < 4; i++) {
        int kk = kq + i*8;
        int k = k0 + kk, n = n0 + nn;
        tile[kk][nn] = (k < KP && n < VC) ? pdirs[(size_t)k*VC + n] : 0.0f;
    }
    __syncthreads();
    int nn2 = t >> 3, q = t & 7;
    int n = n0 + nn2;
    if (n < VC) {
        __nv_bfloat162 p01 = __floats2bfloat162_rn(tile[q*4+0][nn2], tile[q*4+1][nn2]);
        __nv_bfloat162 p23 = __floats2bfloat162_rn(tile[q*4+2][nn2], tile[q*4+3][nn2]);
        __nv_bfloat162* dst = (__nv_bfloat162*)&g_pdB[(size_t)n*KPAD + k0 + q*4];
        dst[0] = p01;
        dst[1] = p23;
    }
}

// ---------------------------------------------------------------------------
__global__ void regress_k(const float* __restrict__ Jreg,
                          const float* __restrict__ vt,
                          const float* __restrict__ sd)
{
    int j = blockIdx.x;
    int chunk = blockIdx.y;
    const int CH = (V_NUM + 13) / 14;
    int v0 = chunk * CH;
    int v1 = min(v0 + CH, V_NUM);
    int t = threadIdx.x;
    int lane = t & 31, w = t >> 5;

    float acc[33];
#pragma unroll
    for (int i = 0; i < 33; i++) acc[i] = 0.f;
    for (int v = v0 + t; v < v1; v += 256) {
        float r = Jreg[j*V_NUM + v];
#pragma unroll
        for (int c = 0; c < 3; c++) acc[c] += r * vt[v*3+c];
#pragma unroll
        for (int i = 0; i < 30; i++) acc[3+i] += r * sd[v*30+i];
    }
    __shared__ float red[8][33];
#pragma unroll
    for (int i = 0; i < 33; i++) {
        float v = acc[i];
#pragma unroll
        for (int o = 16; o; o >>= 1) v += __shfl_xor_sync(0xffffffffu, v, o);
        if (lane == 0) red[w][i] = v;
    }
    __syncthreads();
    if (t < 33) {
        float s = 0.f;
#pragma unroll
        for (int ww = 0; ww < 8; ww++) s += red[ww][t];
        if (t < 3) atomicAdd(&g_Jt0[j*3 + t], s);
        else       atomicAdd(&g_JS[j*30 + (t-3)], s);
    }
}

// ---------------------------------------------------------------------------
// pose_k: 8 batches per block (one warp each).
// ---------------------------------------------------------------------------
__global__ void pose_k(const float* __restrict__ pose,
                       const float* __restrict__ betas,
                       const float* __restrict__ trans)
{
    int warp = threadIdx.x >> 5;
    int lane = threadIdx.x & 31;
    int b = blockIdx.x*8 + warp;
    __shared__ float R[8][24][9];
    __shared__ float Jt[8][24][3];
    __shared__ float Tl[8][24][12];
    __shared__ float Tw[8][24][12];

    if (lane < 24) {
        float rx = pose[b*72 + lane*3 + 0];
        float ry = pose[b*72 + lane*3 + 1];
        float rz = pose[b*72 + lane*3 + 2];
        float ang = sqrtf(rx*rx + ry*ry + rz*rz + 1e-16f);
        float inv = 1.0f/ang;
        float ax = rx*inv, ay = ry*inv, az = rz*inv;
        float s = sinf(ang), c = cosf(ang), tt = 1.0f - c;
        R[warp][lane][0] = c + tt*ax*ax;    R[warp][lane][1] = tt*ax*ay - s*az; R[warp][lane][2] = tt*ax*az + s*ay;
        R[warp][lane][3] = tt*ax*ay + s*az; R[warp][lane][4] = c + tt*ay*ay;    R[warp][lane][5] = tt*ay*az - s*ax;
        R[warp][lane][6] = tt*ax*az - s*ay; R[warp][lane][7] = tt*ay*az + s*ax; R[warp][lane][8] = c + tt*az*az;

        float bet[NBETA];
#pragma unroll
        for (int k = 0; k < NBETA; k++) bet[k] = betas[b*NBETA + k];
#pragma unroll
        for (int c3 = 0; c3 < 3; c3++) {
            float a = g_Jt0[lane*3 + c3];
#pragma unroll
            for (int k = 0; k < NBETA; k++) a += g_JS[lane*30 + c3*10 + k] * bet[k];
            Jt[warp][lane][c3] = a;
        }
    }
    __syncwarp();

    for (int idx = lane; idx < KPAD; idx += 32) {
        float v = 0.0f;
        if (idx < KP) {
            int j = idx/9 + 1, e = idx%9;
            v = R[warp][j][e] - ((e == 0 || e == 4 || e == 8) ? 1.0f : 0.0f);
        }
        g_pfB[b*KPAD + idx] = __float2bfloat16(v);
    }

    if (lane < 24) {
        float tx, ty, tz;
        if (lane == 0) { tx = Jt[warp][0][0]; ty = Jt[warp][0][1]; tz = Jt[warp][0][2]; }
        else {
            int p = c_par[lane];
            tx = Jt[warp][lane][0] - Jt[warp][p][0];
            ty = Jt[warp][lane][1] - Jt[warp][p][1];
            tz = Jt[warp][lane][2] - Jt[warp][p][2];
        }
        Tl[warp][lane][0] = R[warp][lane][0]; Tl[warp][lane][1] = R[warp][lane][1]; Tl[warp][lane][2]  = R[warp][lane][2]; Tl[warp][lane][3]  = tx;
        Tl[warp][lane][4] = R[warp][lane][3]; Tl[warp][lane][5] = R[warp][lane][4]; Tl[warp][lane][6]  = R[warp][lane][5]; Tl[warp][lane][7]  = ty;
        Tl[warp][lane][8] = R[warp][lane][6]; Tl[warp][lane][9] = R[warp][lane][7]; Tl[warp][lane][10] = R[warp][lane][8]; Tl[warp][lane][11] = tz;
    }
    __syncwarp();
    if (lane < 12) Tw[warp][0][lane] = Tl[warp][0][lane];
    __syncwarp();
    for (int i = 1; i < 24; i++) {
        if (lane < 12) {
            int r = lane >> 2, cc = lane & 3;
            int p = c_par[i];
            float v = Tw[warp][p][r*4+0]*Tl[warp][i][0+cc] + Tw[warp][p][r*4+1]*Tl[warp][i][4+cc] + Tw[warp][p][r*4+2]*Tl[warp][i][8+cc];
            if (cc == 3) v += Tw[warp][p][r*4+3];
            Tw[warp][i][lane] = v;
        }
        __syncwarp();
    }
    if (lane < 24) {
        float jx = Jt[warp][lane][0], jy = Jt[warp][lane][1], jz = Jt[warp][lane][2];
        size_t base = (size_t)(b >> 1) * 580 + (b & 1);
#pragma unroll
        for (int r = 0; r < 3; r++) {
            float r0 = Tw[warp][lane][r*4+0], r1 = Tw[warp][lane][r*4+1], r2 = Tw[warp][lane][r*4+2];
            float t3 = Tw[warp][lane][r*4+3] - (r0*jx + r1*jy + r2*jz) + trans[b*3+r];
            int e = lane*12 + r*4;
            g_A2[base + (e+0)*2] = r0;
            g_A2[base + (e+1)*2] = r1;
            g_A2[base + (e+2)*2] = r2;
            g_A2[base + (e+3)*2] = t3;
        }
    }
}

// ---------------------------------------------------------------------------
// Main kernel: bf16 HMMA GEMM (ldmatrix fragments, 3-stage ring) + FFMA2 skinning.
// ---------------------------------------------------------------------------
#define AS_B   (64*80)
#define BS_B   (96*80)
#define AS0b   0
#define BS0b   (3*AS_B)           // 15360
#define STG_ENDb (BS0b + 3*BS_B)  // 38400 B = 9600 floats
#define VP_OFF 0                  // aliased: Vp [64][100] = 25600 B
#define W_OFF  9600
#define BE_OFF (W_OFF + 24*32)
#define SMEM_F (BE_OFF + 64*NBETA)

__global__ void __launch_bounds__(NTHR, 3) lbs_k(
    const float* __restrict__ vt,
    const float* __restrict__ sd,
    const float* __restrict__ wts,
    const float* __restrict__ betas,
    float* __restrict__ out)
{
    __shared__ __align__(16) float smem[SMEM_F];
    u32 sbase = (u32)__cvta_generic_to_shared(smem);

    int t = threadIdx.x;
    int vb = blockIdx.x * 32;
    int n0 = blockIdx.x * 96;
    int b0 = blockIdx.y * 64;
    bool tailv = (vb + 32 > V_NUM);

    // ---- group 0: weights + betas + stage 0 ----
    for (int idx = t; idx < 24*32; idx += NTHR) {
        int j = idx >> 5, vv = idx & 31;
        int v = vb + vv;
        cp4(sbase + (W_OFF + idx)*4, (v < V_NUM) ? &wts[v*24 + j] : wts);
    }
    {
        const float* bsrc = betas + (size_t)b0 * NBETA;
        for (int idx = t; idx < (64*NBETA)/4; idx += NTHR)
            cp16(sbase + BE_OFF*4 + idx*16, bsrc + idx*4);
    }

    auto fill = [&](int buf, int kc) {
        u32 adst = sbase + AS0b + buf*AS_B;
        const __nv_bfloat16* asrc = g_pfB + (size_t)b0*KPAD + kc;
        for (int idx = t; idx < 256; idx += NTHR) {
            int b = idx >> 2, q = idx & 3;
            cp16(adst + b*80 + q*16, asrc + (size_t)b*KPAD + q*8);
        }
        u32 bdst = sbase + BS0b + buf*BS_B;
        for (int idx = t; idx < 384; idx += NTHR) {
            int n = idx >> 2, q = idx & 3;
            int gn = n0 + n;
            const __nv_bfloat16* s = g_pdB + (size_t)(gn < VC ? gn : 0)*KPAD + kc;
            cp16(bdst + n*80 + q*16, s + q*8);
        }
    };

    fill(0, 0);        cp_commit();
    fill(1, KTS);      cp_commit();

    // ---- GEMM: 7 stages x 2 k-steps, ldmatrix + m16n8k16 bf16 ----
    int wid = t >> 5, lane = t & 31;
    int wm = wid & 3;
    int wn = wid >> 2;
    int gid = lane >> 2, tg = lane & 3;

    // ldmatrix lane-address components (bytes, within a stage buffer)
    u32 a_lane_off = (u32)((wm*16 + (lane & 15))*80 + (lane >> 4)*16);
    u32 b_lane_off = (u32)((wn*48 + (lane >> 4)*8 + (lane & 7))*80 + ((lane >> 3) & 1)*16);

    float d[6][4];
#pragma unroll
    for (int f = 0; f < 6; f++)
#pragma unroll
        for (int r = 0; r < 4; r++) d[f][r] = 0.0f;

#pragma unroll 1
    for (int it = 0; it < NSTG; it++) {
        cp_wait<1>();
        __syncthreads();

        int buf = it % 3;
        u32 abase = sbase + AS0b + buf*AS_B + a_lane_off;
        u32 bbase = sbase + BS0b + buf*BS_B + b_lane_off;
#pragma unroll
        for (int ks = 0; ks < 2; ks++) {
            u32 a[4];
            ldsm4(a[0], a[1], a[2], a[3], abase + ks*32);
            u32 b[12];
#pragma unroll
            for (int fp = 0; fp < 3; fp++)
                ldsm4(b[fp*4+0], b[fp*4+1], b[fp*4+2], b[fp*4+3],
                      bbase + fp*16*80 + ks*32);
#pragma unroll
            for (int f = 0; f < 6; f++)
                mma_bf16(d[f], a, b[2*f], b[2*f+1]);
        }

        if (it + 2 < NSTG) fill((it + 2) % 3, (it + 2)*KTS);
        cp_commit();
    }
    __syncthreads();   // all compute done before Vp aliases the stage buffers

    // ---- phase 2 mapping ----
    int vg = t & 7;
    int bg = t >> 3;

    // shape blend (fp32)
    float f2[2][12];
    {
#pragma unroll
        for (int dv = 0; dv < 4; dv++) {
            int v = vb + vg*4 + dv;
            float vt3[3], sdv[30];
            if (v < V_NUM) {
#pragma unroll
                for (int c = 0; c < 3; c++) vt3[c] = vt[v*3+c];
                const float2* s2 = (const float2*)&sd[v*30];
#pragma unroll
                for (int i = 0; i < 15; i++) {
                    float2 dd = s2[i];
                    sdv[2*i] = dd.x; sdv[2*i+1] = dd.y;
                }
            } else {
#pragma unroll
                for (int c = 0; c < 3; c++) vt3[c] = 0.f;
#pragma unroll
                for (int i = 0; i < 30; i++) sdv[i] = 0.f;
            }
#pragma unroll
            for (int bb = 0; bb < 2; bb++) {
                const float* bp = &smem[BE_OFF + (bg*2+bb)*NBETA];
                float a0 = vt3[0], a1 = vt3[1], a2 = vt3[2];
#pragma unroll
                for (int k = 0; k < NBETA; k++) {
                    float be = bp[k];
                    a0 += sdv[k]    * be;
                    a1 += sdv[10+k] * be;
                    a2 += sdv[20+k] * be;
                }
                f2[bb][dv*3+0] = a0; f2[bb][dv*3+1] = a1; f2[bb][dv*3+2] = a2;
            }
        }
    }

    // ---- epilogue: D fragments -> Vp[64][100] ----
    {
        float* Vp = smem + VP_OFF;
        int rb = wm*16 + gid;
#pragma unroll
        for (int f = 0; f < 6; f++) {
            int col = wn*48 + f*8 + 2*tg;
            *(float2*)&Vp[rb*100 + col]     = make_float2(d[f][0], d[f][1]);
            *(float2*)&Vp[(rb+8)*100 + col] = make_float2(d[f][2], d[f][3]);
        }
    }
    __syncthreads();

    // ---- pack accumulators over batch pair ----
    ull xp[12];
    {
        const float* VL = &smem[VP_OFF + (bg*2)*100 + vg*12];
        const float* VH = VL + 100;
        float4 L0 = *(const float4*)&VL[0], L1 = *(const float4*)&VL[4], L2 = *(const float4*)&VL[8];
        float4 H0 = *(const float4*)&VH[0], H1 = *(const float4*)&VH[4], H2 = *(const float4*)&VH[8];
        float L[12] = {L0.x,L0.y,L0.z,L0.w, L1.x,L1.y,L1.z,L1.w, L2.x,L2.y,L2.z,L2.w};
        float H[12] = {H0.x,H0.y,H0.z,H0.w, H1.x,H1.y,H1.z,H1.w, H2.x,H2.y,H2.z,H2.w};
#pragma unroll
        for (int e = 0; e < 12; e++)
            xp[e] = pk(f2[0][e] + L[e], f2[1][e] + H[e]);
    }

    // ---- skinning blend ----
    ull o2[12];
#pragma unroll
    for (int e = 0; e < 12; e++) o2[e] = pk(0.f, 0.f);

    const ulonglong2* Ab = (const ulonglong2*)(g_A2 + ((size_t)(b0 >> 1) + bg)*580);

#pragma unroll 2
    for (int j = 0; j < 24; j++) {
        float4 w4 = *(const float4*)&smem[W_OFF + j*32 + vg*4];
        ull wp[4] = { pk(w4.x,w4.x), pk(w4.y,w4.y), pk(w4.z,w4.z), pk(w4.w,w4.w) };
#pragma unroll
        for (int r = 0; r < 3; r++) {
            ulonglong2 Ar0 = Ab[j*6 + r*2], Ar1 = Ab[j*6 + r*2 + 1];
            ull a0 = Ar0.x, a1 = Ar0.y, a2 = Ar1.x, a3 = Ar1.y;
#pragma unroll
            for (int dv = 0; dv < 4; dv++) {
                ull q = ffma2(a0, xp[dv*3+0],
                        ffma2(a1, xp[dv*3+1],
                        ffma2(a2, xp[dv*3+2], a3)));
                o2[dv*3+r] = ffma2(wp[dv], q, o2[dv*3+r]);
            }
        }
    }

    // ---- store: 6 x STG.64 per batch (8B-aligned always) ----
    int v0 = vb + vg*4;
    if (!tailv) {
#pragma unroll
        for (int s = 0; s < 2; s++) {
            int b = b0 + bg*2 + s;
            float* o = out + ((size_t)b*V_NUM + v0)*3;
#pragma unroll
            for (int k = 0; k < 6; k++) {
                float2 v2;
                v2.x = s ? uhi(o2[2*k])   : ulo(o2[2*k]);
                v2.y = s ? uhi(o2[2*k+1]) : ulo(o2[2*k+1]);
                *(float2*)(o + 2*k) = v2;
            }
        }
    } else {
#pragma unroll
        for (int s = 0; s < 2; s++) {
            int b = b0 + bg*2 + s;
#pragma unroll
            for (int e = 0; e < 12; e++) {
                int v = v0 + e/3;
                if (v < V_NUM) {
                    float val = s ? uhi(o2[e]) : ulo(o2[e]);
                    out[((size_t)b*V_NUM + v)*3 + (e % 3)] = val;
                }
            }
        }
    }
}

extern "C" void kernel_launch(void* const* d_in, const int* in_sizes, int n_in,
                              void* d_out, int out_size)
{
    const float* pose   = (const float*)d_in[0];
    const float* betas  = (const float*)d_in[1];
    const float* trans  = (const float*)d_in[2];
    const float* vt     = (const float*)d_in[3];
    const float* sd     = (const float*)d_in[4];
    const float* pdirs  = (const float*)d_in[5];
    const float* Jreg   = (const float*)d_in[6];
    const float* wts    = (const float*)d_in[7];
    // d_in[8] = parents (fixed SMPL topology, baked into __constant__)

    cvtB_k<<<dim3((VC + 31)/32, KPAD/32), 256>>>(pdirs);
    regress_k<<<dim3(24, 14), 256>>>(Jreg, vt, sd);
    pose_k<<<B_NUM/8, 256>>>(pose, betas, trans);
    dim3 grid((VC + 95)/96, B_NUM/64);   // 216 x 8
    lbs_k<<<grid, NTHR>>>(vt, sd, wts, betas, (float*)d_out);
}

// round 14
// speedup vs baseline: 2.1772x; 1.1688x over previous
#include <cuda_runtime.h>
#include <cuda_bf16.h>
#include <stdint.h>
#include <math.h>

#define V_NUM 6890
#define B_NUM 512
#define J_NUM 24
#define KP    207   // (J-1)*9
#define NBETA 10
#define VC    (V_NUM*3)   // 20670
#define KPAD  256         // 207 pose + pad + 10 shape + 2 vt(double-bf16) + pad
#define KTS   32          // k per stage
#define NSTG  8
#define NTHR  256
#define KSH   224         // k-offset of the shape/vt extension

typedef unsigned long long ull;
typedef unsigned int u32;

__constant__ int c_par[24] = {-1,0,0,0,1,2,3,4,5,6,7,8,9,9,9,12,13,14,16,17,18,19,20,21};

// Scratch (no allocations allowed)
__device__ float g_Jt0[J_NUM*3];
__device__ float g_JS[J_NUM*3*NBETA];
__device__ __align__(16) float g_A2[(B_NUM/2)*580];            // batch-pair-interleaved affines
__device__ __align__(16) __nv_bfloat16 g_pfB[B_NUM*KPAD];      // A: [b][k] = pose_feature | betas | 1,1
__device__ __align__(16) __nv_bfloat16 g_pdB[(size_t)VC*KPAD]; // B: [n][k] = posedirs^T | shapedirs | vt_hi,vt_lo

// ---- packed f32x2 helpers -------------------------------------------------
__device__ __forceinline__ ull pk(float l, float h) {
    ull r; asm("mov.b64 %0, {%1, %2};" : "=l"(r) : "f"(l), "f"(h)); return r;
}
__device__ __forceinline__ float ulo(ull v) {
    float l, h; asm("mov.b64 {%0, %1}, %2;" : "=f"(l), "=f"(h) : "l"(v)); return l;
}
__device__ __forceinline__ float uhi(ull v) {
    float l, h; asm("mov.b64 {%0, %1}, %2;" : "=f"(l), "=f"(h) : "l"(v)); return h;
}
__device__ __forceinline__ ull ffma2(ull a, ull b, ull c) {
    ull r; asm("fma.rn.f32x2 %0, %1, %2, %3;" : "=l"(r) : "l"(a), "l"(b), "l"(c)); return r;
}

// ---- cp.async helpers -----------------------------------------------------
__device__ __forceinline__ void cp16(u32 dst, const void* src) {
    asm volatile("cp.async.ca.shared.global [%0], [%1], 16;" :: "r"(dst), "l"(src));
}
__device__ __forceinline__ void cp4(u32 dst, const void* src) {
    asm volatile("cp.async.ca.shared.global [%0], [%1], 4;" :: "r"(dst), "l"(src));
}
__device__ __forceinline__ void cp_commit() { asm volatile("cp.async.commit_group;"); }
template<int N> __device__ __forceinline__ void cp_wait() {
    asm volatile("cp.async.wait_group %0;" :: "n"(N));
}

// ---- ldmatrix + bf16 mma ----------------------------------------------------
__device__ __forceinline__ void ldsm4(u32& r0, u32& r1, u32& r2, u32& r3, u32 addr) {
    asm volatile("ldmatrix.sync.aligned.m8n8.x4.shared.b16 {%0,%1,%2,%3}, [%4];"
        : "=r"(r0), "=r"(r1), "=r"(r2), "=r"(r3) : "r"(addr));
}
__device__ __forceinline__ void mma_bf16(float* d, const u32* a, u32 b0, u32 b1) {
    asm volatile(
        "mma.sync.aligned.m16n8k16.row.col.f32.bf16.bf16.f32 "
        "{%0,%1,%2,%3}, {%4,%5,%6,%7}, {%8,%9}, {%0,%1,%2,%3};"
        : "+f"(d[0]), "+f"(d[1]), "+f"(d[2]), "+f"(d[3])
        : "r"(a[0]), "r"(a[1]), "r"(a[2]), "r"(a[3]), "r"(b0), "r"(b1));
}

// ---------------------------------------------------------------------------
// cvtB_k: build the extended B matrix.
//   k <  207 : bf16(posedirs[k][n])      (32x32 smem transpose)
//   k in [224,234): bf16(shapedirs[n/3][n%3][k-224])
//   k == 234 : vt_hi = bf16(vt[n]);  k == 235 : vt_lo = bf16(vt[n]-vt_hi)
//   else 0.  Block (0,0) also zeroes the regress accumulators.
// ---------------------------------------------------------------------------
__global__ void cvtB_k(const float* __restrict__ pdirs,
                       const float* __restrict__ vt,
                       const float* __restrict__ sd)
{
    __shared__ float tile[32][33];
    int t = threadIdx.x;   // 256
    if (blockIdx.x == 0 && blockIdx.y == 0) {
        if (t < J_NUM*3) g_Jt0[t] = 0.0f;
        for (int i = t; i < J_NUM*30; i += 256) g_JS[i] = 0.0f;
    }
    int n0 = blockIdx.x * 32;
    int k0 = blockIdx.y * 32;

    if (k0 == KSH) {
        // shape/vt extension block: direct gather
        int nn2 = t >> 3, q = t & 7;
        int n = n0 + nn2;
        if (n < VC) {
            int v = n / 3, c = n % 3;
            float vtv = vt[n];
            __nv_bfloat16 hi = __float2bfloat16(vtv);
            float lo = vtv - __bfloat162float(hi);
            __nv_bfloat16 vals[4];
#pragma unroll
            for (int i = 0; i < 4; i++) {
                int kk = q*4 + i;
                float x = 0.0f;
                if (kk < NBETA)      x = sd[v*30 + c*10 + kk];
                vals[i] = __float2bfloat16(x);
                if (kk == 10) vals[i] = hi;
                if (kk == 11) vals[i] = __float2bfloat16(lo);
            }
            __nv_bfloat162* dst = (__nv_bfloat162*)&g_pdB[(size_t)n*KPAD + k0 + q*4];
            dst[0] = __nv_bfloat162{vals[0], vals[1]};
            dst[1] = __nv_bfloat162{vals[2], vals[3]};
        }
        return;
    }

    int nn = t & 31, kq = t >> 5;
#pragma unroll
    for (int i = 0; i < 4; i++) {
        int kk = kq + i*8;
        int k = k0 + kk, n = n0 + nn;
        tile[kk][nn] = (k < KP && n < VC) ? pdirs[(size_t)k*VC + n] : 0.0f;
    }
    __syncthreads();
    int nn2 = t >> 3, q = t & 7;
    int n = n0 + nn2;
    if (n < VC) {
        __nv_bfloat162 p01 = __floats2bfloat162_rn(tile[q*4+0][nn2], tile[q*4+1][nn2]);
        __nv_bfloat162 p23 = __floats2bfloat162_rn(tile[q*4+2][nn2], tile[q*4+3][nn2]);
        __nv_bfloat162* dst = (__nv_bfloat162*)&g_pdB[(size_t)n*KPAD + k0 + q*4];
        dst[0] = p01;
        dst[1] = p23;
    }
}

// ---------------------------------------------------------------------------
__global__ void regress_k(const float* __restrict__ Jreg,
                          const float* __restrict__ vt,
                          const float* __restrict__ sd)
{
    int j = blockIdx.x;
    int chunk = blockIdx.y;
    const int CH = (V_NUM + 13) / 14;
    int v0 = chunk * CH;
    int v1 = min(v0 + CH, V_NUM);
    int t = threadIdx.x;
    int lane = t & 31, w = t >> 5;

    float acc[33];
#pragma unroll
    for (int i = 0; i < 33; i++) acc[i] = 0.f;
    for (int v = v0 + t; v < v1; v += 256) {
        float r = Jreg[j*V_NUM + v];
#pragma unroll
        for (int c = 0; c < 3; c++) acc[c] += r * vt[v*3+c];
#pragma unroll
        for (int i = 0; i < 30; i++) acc[3+i] += r * sd[v*30+i];
    }
    __shared__ float red[8][33];
#pragma unroll
    for (int i = 0; i < 33; i++) {
        float v = acc[i];
#pragma unroll
        for (int o = 16; o; o >>= 1) v += __shfl_xor_sync(0xffffffffu, v, o);
        if (lane == 0) red[w][i] = v;
    }
    __syncthreads();
    if (t < 33) {
        float s = 0.f;
#pragma unroll
        for (int ww = 0; ww < 8; ww++) s += red[ww][t];
        if (t < 3) atomicAdd(&g_Jt0[j*3 + t], s);
        else       atomicAdd(&g_JS[j*30 + (t-3)], s);
    }
}

// ---------------------------------------------------------------------------
// pose_k: 8 batches per block; extended A row: pf | betas | 1,1.
// ---------------------------------------------------------------------------
__global__ void pose_k(const float* __restrict__ pose,
                       const float* __restrict__ betas,
                       const float* __restrict__ trans)
{
    int warp = threadIdx.x >> 5;
    int lane = threadIdx.x & 31;
    int b = blockIdx.x*8 + warp;
    __shared__ float R[8][24][9];
    __shared__ float Jt[8][24][3];
    __shared__ float Tl[8][24][12];
    __shared__ float Tw[8][24][12];

    if (lane < 24) {
        float rx = pose[b*72 + lane*3 + 0];
        float ry = pose[b*72 + lane*3 + 1];
        float rz = pose[b*72 + lane*3 + 2];
        float ang = sqrtf(rx*rx + ry*ry + rz*rz + 1e-16f);
        float inv = 1.0f/ang;
        float ax = rx*inv, ay = ry*inv, az = rz*inv;
        float s = sinf(ang), c = cosf(ang), tt = 1.0f - c;
        R[warp][lane][0] = c + tt*ax*ax;    R[warp][lane][1] = tt*ax*ay - s*az; R[warp][lane][2] = tt*ax*az + s*ay;
        R[warp][lane][3] = tt*ax*ay + s*az; R[warp][lane][4] = c + tt*ay*ay;    R[warp][lane][5] = tt*ay*az - s*ax;
        R[warp][lane][6] = tt*ax*az - s*ay; R[warp][lane][7] = tt*ay*az + s*ax; R[warp][lane][8] = c + tt*az*az;

        float bet[NBETA];
#pragma unroll
        for (int k = 0; k < NBETA; k++) bet[k] = betas[b*NBETA + k];
#pragma unroll
        for (int c3 = 0; c3 < 3; c3++) {
            float a = g_Jt0[lane*3 + c3];
#pragma unroll
            for (int k = 0; k < NBETA; k++) a += g_JS[lane*30 + c3*10 + k] * bet[k];
            Jt[warp][lane][c3] = a;
        }
    }
    __syncwarp();

    // extended A row
    for (int idx = lane; idx < KPAD; idx += 32) {
        float v = 0.0f;
        if (idx < KP) {
            int j = idx/9 + 1, e = idx%9;
            v = R[warp][j][e] - ((e == 0 || e == 4 || e == 8) ? 1.0f : 0.0f);
        } else if (idx >= KSH && idx < KSH + NBETA) {
            v = betas[b*NBETA + (idx - KSH)];
        } else if (idx == KSH + 10 || idx == KSH + 11) {
            v = 1.0f;
        }
        g_pfB[b*KPAD + idx] = __float2bfloat16(v);
    }

    if (lane < 24) {
        float tx, ty, tz;
        if (lane == 0) { tx = Jt[warp][0][0]; ty = Jt[warp][0][1]; tz = Jt[warp][0][2]; }
        else {
            int p = c_par[lane];
            tx = Jt[warp][lane][0] - Jt[warp][p][0];
            ty = Jt[warp][lane][1] - Jt[warp][p][1];
            tz = Jt[warp][lane][2] - Jt[warp][p][2];
        }
        Tl[warp][lane][0] = R[warp][lane][0]; Tl[warp][lane][1] = R[warp][lane][1]; Tl[warp][lane][2]  = R[warp][lane][2]; Tl[warp][lane][3]  = tx;
        Tl[warp][lane][4] = R[warp][lane][3]; Tl[warp][lane][5] = R[warp][lane][4]; Tl[warp][lane][6]  = R[warp][lane][5]; Tl[warp][lane][7]  = ty;
        Tl[warp][lane][8] = R[warp][lane][6]; Tl[warp][lane][9] = R[warp][lane][7]; Tl[warp][lane][10] = R[warp][lane][8]; Tl[warp][lane][11] = tz;
    }
    __syncwarp();
    if (lane < 12) Tw[warp][0][lane] = Tl[warp][0][lane];
    __syncwarp();
    for (int i = 1; i < 24; i++) {
        if (lane < 12) {
            int r = lane >> 2, cc = lane & 3;
            int p = c_par[i];
            float v = Tw[warp][p][r*4+0]*Tl[warp][i][0+cc] + Tw[warp][p][r*4+1]*Tl[warp][i][4+cc] + Tw[warp][p][r*4+2]*Tl[warp][i][8+cc];
            if (cc == 3) v += Tw[warp][p][r*4+3];
            Tw[warp][i][lane] = v;
        }
        __syncwarp();
    }
    if (lane < 24) {
        float jx = Jt[warp][lane][0], jy = Jt[warp][lane][1], jz = Jt[warp][lane][2];
        size_t base = (size_t)(b >> 1) * 580 + (b & 1);
#pragma unroll
        for (int r = 0; r < 3; r++) {
            float r0 = Tw[warp][lane][r*4+0], r1 = Tw[warp][lane][r*4+1], r2 = Tw[warp][lane][r*4+2];
            float t3 = Tw[warp][lane][r*4+3] - (r0*jx + r1*jy + r2*jz) + trans[b*3+r];
            int e = lane*12 + r*4;
            g_A2[base + (e+0)*2] = r0;
            g_A2[base + (e+1)*2] = r1;
            g_A2[base + (e+2)*2] = r2;
            g_A2[base + (e+3)*2] = t3;
        }
    }
}

// ---------------------------------------------------------------------------
// Main kernel: extended bf16 GEMM (v_posed in one shot) + FFMA2 skinning.
// ---------------------------------------------------------------------------
#define AS_B   (64*80)
#define BS_B   (96*80)
#define AS0b   0
#define BS0b   (3*AS_B)           // 15360
#define STG_ENDb (BS0b + 3*BS_B)  // 38400 B = 9600 floats
#define VP_OFF 0                  // aliased: Vp [64][100] = 25600 B
#define W_OFF  9600
#define SMEM_F (W_OFF + 24*32)    // 10368 floats = 41472 B

__global__ void __launch_bounds__(NTHR, 3) lbs_k(
    const float* __restrict__ wts,
    float* __restrict__ out)
{
    __shared__ __align__(16) float smem[SMEM_F];
    u32 sbase = (u32)__cvta_generic_to_shared(smem);

    int t = threadIdx.x;
    int vb = blockIdx.x * 32;
    int n0 = blockIdx.x * 96;
    int b0 = blockIdx.y * 64;
    bool tailv = (vb + 32 > V_NUM);

    // ---- group 0: weights + stage 0 ----
    for (int idx = t; idx < 24*32; idx += NTHR) {
        int j = idx >> 5, vv = idx & 31;
        int v = vb + vv;
        cp4(sbase + (W_OFF + idx)*4, (v < V_NUM) ? &wts[v*24 + j] : wts);
    }

    auto fill = [&](int buf, int kc) {
        u32 adst = sbase + AS0b + buf*AS_B;
        const __nv_bfloat16* asrc = g_pfB + (size_t)b0*KPAD + kc;
        for (int idx = t; idx < 256; idx += NTHR) {
            int b = idx >> 2, q = idx & 3;
            cp16(adst + b*80 + q*16, asrc + (size_t)b*KPAD + q*8);
        }
        u32 bdst = sbase + BS0b + buf*BS_B;
        for (int idx = t; idx < 384; idx += NTHR) {
            int n = idx >> 2, q = idx & 3;
            int gn = n0 + n;
            const __nv_bfloat16* s = g_pdB + (size_t)(gn < VC ? gn : 0)*KPAD + kc;
            cp16(bdst + n*80 + q*16, s + q*8);
        }
    };

    fill(0, 0);        cp_commit();
    fill(1, KTS);      cp_commit();

    // ---- GEMM: 8 stages x 2 k-steps, ldmatrix + m16n8k16 bf16 ----
    int wid = t >> 5, lane = t & 31;
    int wm = wid & 3;
    int wn = wid >> 2;
    int gid = lane >> 2, tg = lane & 3;

    u32 a_lane_off = (u32)((wm*16 + (lane & 15))*80 + (lane >> 4)*16);
    u32 b_lane_off = (u32)((wn*48 + (lane >> 4)*8 + (lane & 7))*80 + ((lane >> 3) & 1)*16);

    float d[6][4];
#pragma unroll
    for (int f = 0; f < 6; f++)
#pragma unroll
        for (int r = 0; r < 4; r++) d[f][r] = 0.0f;

#pragma unroll 1
    for (int it = 0; it < NSTG; it++) {
        cp_wait<1>();
        __syncthreads();

        int buf = it % 3;
        u32 abase = sbase + AS0b + buf*AS_B + a_lane_off;
        u32 bbase = sbase + BS0b + buf*BS_B + b_lane_off;
#pragma unroll
        for (int ks = 0; ks < 2; ks++) {
            u32 a[4];
            ldsm4(a[0], a[1], a[2], a[3], abase + ks*32);
            u32 b[12];
#pragma unroll
            for (int fp = 0; fp < 3; fp++)
                ldsm4(b[fp*4+0], b[fp*4+1], b[fp*4+2], b[fp*4+3],
                      bbase + fp*16*80 + ks*32);
#pragma unroll
            for (int f = 0; f < 6; f++)
                mma_bf16(d[f], a, b[2*f], b[2*f+1]);
        }

        if (it + 2 < NSTG) fill((it + 2) % 3, (it + 2)*KTS);
        cp_commit();
    }
    __syncthreads();   // all compute done before Vp aliases the stage buffers

    // ---- epilogue: D fragments -> Vp[64][100] (= full v_posed) ----
    {
        float* Vp = smem + VP_OFF;
        int rb = wm*16 + gid;
#pragma unroll
        for (int f = 0; f < 6; f++) {
            int col = wn*48 + f*8 + 2*tg;
            *(float2*)&Vp[rb*100 + col]     = make_float2(d[f][0], d[f][1]);
            *(float2*)&Vp[(rb+8)*100 + col] = make_float2(d[f][2], d[f][3]);
        }
    }
    __syncthreads();

    // ---- phase 2 mapping ----
    int vg = t & 7;
    int bg = t >> 3;

    // pack v_posed over batch pair
    ull xp[12];
    {
        const float* VL = &smem[VP_OFF + (bg*2)*100 + vg*12];
        const float* VH = VL + 100;
        float4 L0 = *(const float4*)&VL[0], L1 = *(const float4*)&VL[4], L2 = *(const float4*)&VL[8];
        float4 H0 = *(const float4*)&VH[0], H1 = *(const float4*)&VH[4], H2 = *(const float4*)&VH[8];
        float L[12] = {L0.x,L0.y,L0.z,L0.w, L1.x,L1.y,L1.z,L1.w, L2.x,L2.y,L2.z,L2.w};
        float H[12] = {H0.x,H0.y,H0.z,H0.w, H1.x,H1.y,H1.z,H1.w, H2.x,H2.y,H2.z,H2.w};
#pragma unroll
        for (int e = 0; e < 12; e++)
            xp[e] = pk(L[e], H[e]);
    }

    // ---- skinning blend (A from L2-resident gmem) ----
    ull o2[12];
#pragma unroll
    for (int e = 0; e < 12; e++) o2[e] = pk(0.f, 0.f);

    const ulonglong2* Ab = (const ulonglong2*)(g_A2 + ((size_t)(b0 >> 1) + bg)*580);

#pragma unroll 2
    for (int j = 0; j < 24; j++) {
        float4 w4 = *(const float4*)&smem[W_OFF + j*32 + vg*4];
        ull wp[4] = { pk(w4.x,w4.x), pk(w4.y,w4.y), pk(w4.z,w4.z), pk(w4.w,w4.w) };
#pragma unroll
        for (int r = 0; r < 3; r++) {
            ulonglong2 Ar0 = Ab[j*6 + r*2], Ar1 = Ab[j*6 + r*2 + 1];
            ull a0 = Ar0.x, a1 = Ar0.y, a2 = Ar1.x, a3 = Ar1.y;
#pragma unroll
            for (int dv = 0; dv < 4; dv++) {
                ull q = ffma2(a0, xp[dv*3+0],
                        ffma2(a1, xp[dv*3+1],
                        ffma2(a2, xp[dv*3+2], a3)));
                o2[dv*3+r] = ffma2(wp[dv], q, o2[dv*3+r]);
            }
        }
    }

    // ---- store: 6 x STG.64 per batch ----
    int v0 = vb + vg*4;
    if (!tailv) {
#pragma unroll
        for (int s = 0; s < 2; s++) {
            int b = b0 + bg*2 + s;
            float* o = out + ((size_t)b*V_NUM + v0)*3;
#pragma unroll
            for (int k = 0; k < 6; k++) {
                float2 v2;
                v2.x = s ? uhi(o2[2*k])   : ulo(o2[2*k]);
                v2.y = s ? uhi(o2[2*k+1]) : ulo(o2[2*k+1]);
                *(float2*)(o + 2*k) = v2;
            }
        }
    } else {
#pragma unroll
        for (int s = 0; s < 2; s++) {
            int b = b0 + bg*2 + s;
#pragma unroll
            for (int e = 0; e < 12; e++) {
                int v = v0 + e/3;
                if (v < V_NUM) {
                    float val = s ? uhi(o2[e]) : ulo(o2[e]);
                    out[((size_t)b*V_NUM + v)*3 + (e % 3)] = val;
                }
            }
        }
    }
}

extern "C" void kernel_launch(void* const* d_in, const int* in_sizes, int n_in,
                              void* d_out, int out_size)
{
    const float* pose   = (const float*)d_in[0];
    const float* betas  = (const float*)d_in[1];
    const float* trans  = (const float*)d_in[2];
    const float* vt     = (const float*)d_in[3];
    const float* sd     = (const float*)d_in[4];
    const float* pdirs  = (const float*)d_in[5];
    const float* Jreg   = (const float*)d_in[6];
    const float* wts    = (const float*)d_in[7];
    // d_in[8] = parents (fixed SMPL topology, baked into __constant__)

    cvtB_k<<<dim3((VC + 31)/32, KPAD/32), 256>>>(pdirs, vt, sd);   // 646 x 8
    regress_k<<<dim3(24, 14), 256>>>(Jreg, vt, sd);
    pose_k<<<B_NUM/8, 256>>>(pose, betas, trans);
    dim3 grid((VC + 95)/96, B_NUM/64);   // 216 x 8
    lbs_k<<<grid, NTHR>>>(wts, (float*)d_out);
}